// round 4
// baseline (speedup 1.0000x reference)
#include <cuda_runtime.h>
#include <mma.h>
#include <cstdint>

using namespace nvcuda;

#define NUSER 200000
#define NREPO 100000
#define NEDGE 1500000
#define DD    128
#define SCHUNK 4096
#define NB_U ((NUSER + SCHUNK - 1) / SCHUNK)   // 49
#define NB_R ((NREPO + SCHUNK - 1) / SCHUNK)   // 25

// ---------------- scratch (__device__ globals; no allocations) ----------------
__device__ int g_is64;
__device__ int g_deg_u[NUSER];
__device__ int g_deg_r[NREPO];
__device__ int g_rp_u[NUSER + 1];
__device__ int g_rp_r[NREPO + 1];
__device__ int g_fill_u[NUSER];
__device__ int g_fill_r[NREPO];
__device__ int g_adj_u[NEDGE];
__device__ int g_adj_r[NEDGE];
__device__ int g_bsum[2 * 64];
__device__ __align__(128) float g_mean_u[(size_t)NUSER * DD];
__device__ __align__(128) float g_mean_r[(size_t)NREPO * DD];
__device__ __align__(128) float g_user_h[(size_t)NUSER * DD];
__device__ __align__(128) float g_repo_h[(size_t)NREPO * DD];

// ---------------- edge dtype probe + accessors ----------------
// If edge data is int64 (little-endian), odd 32-bit words are high halves of
// small nonnegative indices => all zero. If int32, they're real indices.
__global__ void probe_kernel(const int* __restrict__ e32) {
    __shared__ int nonzero;
    if (threadIdx.x == 0) nonzero = 0;
    __syncthreads();
    if (e32[threadIdx.x * 2 + 1] != 0) atomicOr(&nonzero, 1);
    __syncthreads();
    if (threadIdx.x == 0) g_is64 = (nonzero ? 0 : 1);
}

__device__ __forceinline__ int edge_at(const void* edges, int row, int i, int is64) {
    if (is64) {
        long long v = ((const long long*)edges)[(size_t)row * NEDGE + i];
        return (int)v;
    }
    return ((const int*)edges)[(size_t)row * NEDGE + i];
}

__device__ __forceinline__ int clampi(int v, int hi) {
    return v < 0 ? 0 : (v >= hi ? hi - 1 : v);
}

// ---------------- CSR build ----------------
__global__ void zero_deg_kernel() {
    int i = blockIdx.x * blockDim.x + threadIdx.x;
    int stride = gridDim.x * blockDim.x;
    for (int j = i; j < NUSER; j += stride) g_deg_u[j] = 0;
    for (int j = i; j < NREPO; j += stride) g_deg_r[j] = 0;
}

__global__ void degree_kernel(const void* __restrict__ edges) {
    int is64 = g_is64;
    int stride = gridDim.x * blockDim.x;
    for (int i = blockIdx.x * blockDim.x + threadIdx.x; i < NEDGE; i += stride) {
        int u = clampi(edge_at(edges, 0, i, is64), NUSER);
        int r = clampi(edge_at(edges, 1, i, is64), NREPO);
        atomicAdd(&g_deg_u[u], 1);
        atomicAdd(&g_deg_r[r], 1);
    }
}

__global__ void scan1_kernel() {
    int side = blockIdx.y;
    int nb = side ? NB_R : NB_U;
    int b = blockIdx.x;
    if (b >= nb) return;
    int n = side ? NREPO : NUSER;
    const int* deg = side ? g_deg_r : g_deg_u;
    int* rp = side ? g_rp_r : g_rp_u;

    int tid = threadIdx.x;
    int lane = tid & 31, w = tid >> 5;
    int base = b * SCHUNK + tid * 4;

    int v[4];
    int t = 0;
#pragma unroll
    for (int j = 0; j < 4; j++) {
        int i = base + j;
        v[j] = (i < n) ? deg[i] : 0;
        t += v[j];
    }
    __shared__ int wsum[32];
    int inc = t;
#pragma unroll
    for (int o = 1; o < 32; o <<= 1) {
        int x = __shfl_up_sync(~0u, inc, o);
        if (lane >= o) inc += x;
    }
    if (lane == 31) wsum[w] = inc;
    __syncthreads();
    if (w == 0) {
        int s = wsum[lane];
#pragma unroll
        for (int o = 1; o < 32; o <<= 1) {
            int x = __shfl_up_sync(~0u, s, o);
            if (lane >= o) s += x;
        }
        wsum[lane] = s;
    }
    __syncthreads();
    int ex = inc - t + (w > 0 ? wsum[w - 1] : 0);
    int run = ex;
#pragma unroll
    for (int j = 0; j < 4; j++) {
        int i = base + j;
        if (i < n) rp[i] = run;
        run += v[j];
    }
    if (tid == 1023) g_bsum[side * 64 + b] = run;
}

__global__ void scan2_kernel() {
    int tid = threadIdx.x;
    if (tid < 2) {
        int nb = tid ? NB_R : NB_U;
        int* bs = g_bsum + tid * 64;
        int s = 0;
        for (int i = 0; i < nb; i++) { int x = bs[i]; bs[i] = s; s += x; }
    }
}

__global__ void scan3_kernel() {
    int side = blockIdx.y;
    int nb = side ? NB_R : NB_U;
    int b = blockIdx.x;
    if (b >= nb) return;
    int n = side ? NREPO : NUSER;
    int* rp = side ? g_rp_r : g_rp_u;
    int* fill = side ? g_fill_r : g_fill_u;
    int off = g_bsum[side * 64 + b];
    int base = b * SCHUNK + threadIdx.x * 4;
#pragma unroll
    for (int j = 0; j < 4; j++) {
        int i = base + j;
        if (i < n) {
            int x = rp[i] + off;
            rp[i] = x;
            fill[i] = x;
        }
    }
    if (b == 0 && threadIdx.x == 0) rp[n] = NEDGE;
}

__global__ void place_kernel(const void* __restrict__ edges) {
    int is64 = g_is64;
    int stride = gridDim.x * blockDim.x;
    for (int i = blockIdx.x * blockDim.x + threadIdx.x; i < NEDGE; i += stride) {
        int u = clampi(edge_at(edges, 0, i, is64), NUSER);
        int r = clampi(edge_at(edges, 1, i, is64), NREPO);
        g_adj_r[atomicAdd(&g_fill_r[r], 1)] = u;
        g_adj_u[atomicAdd(&g_fill_u[u], 1)] = r;
    }
}

// ---------------- gather-mean: one warp per destination row ----------------
// srcSel: 0 = ext_src param, 1 = g_user_h, 2 = g_repo_h
// dstRepo: 1 -> dst g_mean_r (rp_r/adj_r), 0 -> dst g_mean_u (rp_u/adj_u)
__global__ void gather_mean_kernel(const float* __restrict__ ext_src,
                                   int srcSel, int dstRepo, int rows) {
    const float* src = (srcSel == 0) ? ext_src : (srcSel == 1 ? g_user_h : g_repo_h);
    float* dst = dstRepo ? g_mean_r : g_mean_u;
    const int* rp = dstRepo ? g_rp_r : g_rp_u;
    const int* adj = dstRepo ? g_adj_r : g_adj_u;

    int warp = (blockIdx.x * blockDim.x + threadIdx.x) >> 5;
    if (warp >= rows) return;
    int lane = threadIdx.x & 31;
    int beg = rp[warp], end = rp[warp + 1];

    float4 a0 = make_float4(0.f, 0.f, 0.f, 0.f);
    float4 a1 = a0, a2 = a0, a3 = a0;
    int j = beg;
    for (; j + 4 <= end; j += 4) {
        int n0 = adj[j], n1 = adj[j + 1], n2 = adj[j + 2], n3 = adj[j + 3];
        float4 v0 = ((const float4*)(src + (size_t)n0 * DD))[lane];
        float4 v1 = ((const float4*)(src + (size_t)n1 * DD))[lane];
        float4 v2 = ((const float4*)(src + (size_t)n2 * DD))[lane];
        float4 v3 = ((const float4*)(src + (size_t)n3 * DD))[lane];
        a0.x += v0.x; a0.y += v0.y; a0.z += v0.z; a0.w += v0.w;
        a1.x += v1.x; a1.y += v1.y; a1.z += v1.z; a1.w += v1.w;
        a2.x += v2.x; a2.y += v2.y; a2.z += v2.z; a2.w += v2.w;
        a3.x += v3.x; a3.y += v3.y; a3.z += v3.z; a3.w += v3.w;
    }
    for (; j < end; j++) {
        float4 v = ((const float4*)(src + (size_t)adj[j] * DD))[lane];
        a0.x += v.x; a0.y += v.y; a0.z += v.z; a0.w += v.w;
    }
    float4 s;
    s.x = (a0.x + a1.x) + (a2.x + a3.x);
    s.y = (a0.y + a1.y) + (a2.y + a3.y);
    s.z = (a0.z + a1.z) + (a2.z + a3.z);
    s.w = (a0.w + a1.w) + (a2.w + a3.w);
    float sc = 1.f / (float)max(end - beg, 1);
    s.x *= sc; s.y *= sc; s.z *= sc; s.w *= sc;
    ((float4*)(dst + (size_t)warp * DD))[lane] = s;
}

// ---------------- fused SAGE GEMM via wmma (tf32) ----------------
// out = relu?( [mean | X](rows x 256) @ [Wl; Wr](256 x 128) + bias )
#define BM 64
#define BK 32
#define ALD 40
#define WLD 136
#define CLD 132
#define SMEM_FLOATS 8448

__global__ void __launch_bounds__(256)
gemm_wmma(int meanRepo,
          const float* __restrict__ ext_x,
          int xSel,                            // 0 ext, 1 g_user_h, 2 g_repo_h
          const float* __restrict__ Wl,
          const float* __restrict__ Wr,
          const float* __restrict__ bias,
          float* __restrict__ ext_out,
          int outSel,                          // 0 ext, 1 g_user_h, 2 g_repo_h
          int rows, int relu) {
    __shared__ __align__(16) float smem_s[SMEM_FLOATS];
    float* sA = smem_s;                // [BM][ALD]
    float* sW = smem_s + BM * ALD;     // [BK][WLD]

    const float* meanp = meanRepo ? g_mean_r : g_mean_u;
    const float* xp = (xSel == 0) ? ext_x : (xSel == 1 ? g_user_h : g_repo_h);
    float* outp = (outSel == 0) ? ext_out : (outSel == 1 ? g_user_h : g_repo_h);

    const int t = threadIdx.x;
    const int w = t >> 5;
    const int blockRow = blockIdx.x * BM;

    wmma::fragment<wmma::accumulator, 16, 16, 8, float> acc[4];
#pragma unroll
    for (int rf = 0; rf < 4; rf++) wmma::fill_fragment(acc[rf], 0.f);

    const int arow = t >> 2;
    const int acol = (t & 3) * 8;
    const int grow = min(blockRow + arow, rows - 1);
    const int wrow = t >> 3;
    const int wcol = (t & 7) * 16;

#pragma unroll 1
    for (int kc = 0; kc < 8; kc++) {
        {
            const float* Asrc = (kc < 4) ? meanp : xp;
            int gcol = ((kc < 4) ? kc * BK : (kc - 4) * BK) + acol;
            const float* p = Asrc + (size_t)grow * DD + gcol;
            float4 v0 = *(const float4*)(p);
            float4 v1 = *(const float4*)(p + 4);
            *(float4*)(sA + arow * ALD + acol) = v0;
            *(float4*)(sA + arow * ALD + acol + 4) = v1;
        }
        {
            const float* Wsrc = (kc < 4) ? Wl : Wr;
            int wk = ((kc < 4) ? kc * BK : (kc - 4) * BK) + wrow;
            const float* p = Wsrc + (size_t)wk * DD + wcol;
            float* d = sW + wrow * WLD + wcol;
            *(float4*)(d + 0) = *(const float4*)(p + 0);
            *(float4*)(d + 4) = *(const float4*)(p + 4);
            *(float4*)(d + 8) = *(const float4*)(p + 8);
            *(float4*)(d + 12) = *(const float4*)(p + 12);
        }
        __syncthreads();

#pragma unroll
        for (int ks = 0; ks < 4; ks++) {
            wmma::fragment<wmma::matrix_b, 16, 16, 8, wmma::precision::tf32, wmma::row_major> bf;
            wmma::load_matrix_sync(bf, sW + ks * 8 * WLD + w * 16, WLD);
#pragma unroll
            for (int i = 0; i < bf.num_elements; i++) bf.x[i] = wmma::__float_to_tf32(bf.x[i]);
#pragma unroll
            for (int rf = 0; rf < 4; rf++) {
                wmma::fragment<wmma::matrix_a, 16, 16, 8, wmma::precision::tf32, wmma::row_major> af;
                wmma::load_matrix_sync(af, sA + rf * 16 * ALD + ks * 8, ALD);
#pragma unroll
                for (int i = 0; i < af.num_elements; i++) af.x[i] = wmma::__float_to_tf32(af.x[i]);
                wmma::mma_sync(acc[rf], af, bf, acc[rf]);
            }
        }
        __syncthreads();
    }

    float* sC = smem_s;   // [BM][CLD]
#pragma unroll
    for (int rf = 0; rf < 4; rf++)
        wmma::store_matrix_sync(sC + rf * 16 * CLD + w * 16, acc[rf], CLD, wmma::mem_row_major);
    __syncthreads();

    for (int e = t; e < BM * (DD / 4); e += 256) {
        int row = e >> 5;
        int c4 = (e & 31) * 4;
        if (blockRow + row < rows) {
            float4 v = *(float4*)(sC + row * CLD + c4);
            float4 bv = *(const float4*)(bias + c4);
            v.x += bv.x; v.y += bv.y; v.z += bv.z; v.w += bv.w;
            if (relu) {
                v.x = fmaxf(v.x, 0.f); v.y = fmaxf(v.y, 0.f);
                v.z = fmaxf(v.z, 0.f); v.w = fmaxf(v.w, 0.f);
            }
            *(float4*)(outp + (size_t)(blockRow + row) * DD + c4) = v;
        }
    }
}

// ---------------- launch ----------------
extern "C" void kernel_launch(void* const* d_in, const int* in_sizes, int n_in,
                              void* d_out, int out_size) {
    const float* x_user = (const float*)d_in[0];
    const float* x_repo = (const float*)d_in[1];
    const void* edges = d_in[2];
    const float* Wl1s = (const float*)d_in[3];
    const float* bl1s = (const float*)d_in[4];
    const float* Wr1s = (const float*)d_in[5];
    const float* Wl1r = (const float*)d_in[6];
    const float* bl1r = (const float*)d_in[7];
    const float* Wr1r = (const float*)d_in[8];
    const float* Wl2s = (const float*)d_in[9];
    const float* bl2s = (const float*)d_in[10];
    const float* Wr2s = (const float*)d_in[11];
    const float* Wl2r = (const float*)d_in[12];
    const float* bl2r = (const float*)d_in[13];
    const float* Wr2r = (const float*)d_in[14];

    float* out_user = (float*)d_out;
    float* out_repo = out_user + (size_t)NUSER * DD;

    // ---- edge dtype probe + CSR build (once; reused by both layers) ----
    probe_kernel<<<1, 256>>>((const int*)edges);
    zero_deg_kernel<<<512, 512>>>();
    degree_kernel<<<2048, 256>>>(edges);
    dim3 gs(NB_U, 2);
    scan1_kernel<<<gs, 1024>>>();
    scan2_kernel<<<1, 32>>>();
    scan3_kernel<<<gs, 1024>>>();
    place_kernel<<<2048, 256>>>(edges);

    // ---- layer 1 ----
    gather_mean_kernel<<<(NREPO + 7) / 8, 256>>>(x_user, 0, 1, NREPO);
    gather_mean_kernel<<<(NUSER + 7) / 8, 256>>>(x_repo, 0, 0, NUSER);
    gemm_wmma<<<(NREPO + BM - 1) / BM, 256>>>(1, x_repo, 0, Wl1s, Wr1s, bl1s,
                                              nullptr, 2, NREPO, 1);
    gemm_wmma<<<(NUSER + BM - 1) / BM, 256>>>(0, x_user, 0, Wl1r, Wr1r, bl1r,
                                              nullptr, 1, NUSER, 1);

    // ---- layer 2 ----
    gather_mean_kernel<<<(NREPO + 7) / 8, 256>>>(nullptr, 1, 1, NREPO);
    gather_mean_kernel<<<(NUSER + 7) / 8, 256>>>(nullptr, 2, 0, NUSER);
    gemm_wmma<<<(NREPO + BM - 1) / BM, 256>>>(1, nullptr, 2, Wl2s, Wr2s, bl2s,
                                              out_repo, 0, NREPO, 0);
    gemm_wmma<<<(NUSER + BM - 1) / BM, 256>>>(0, nullptr, 1, Wl2r, Wr2r, bl2r,
                                              out_user, 0, NUSER, 0);
}

// round 5
// speedup vs baseline: 1.2420x; 1.2420x over previous
#include <cuda_runtime.h>
#include <cstdint>

#define NUSER 200000
#define NREPO 100000
#define NEDGE 1500000
#define DD    128
#define SCHUNK 4096
#define NB_U ((NUSER + SCHUNK - 1) / SCHUNK)   // 49
#define NB_R ((NREPO + SCHUNK - 1) / SCHUNK)   // 25

// ---------------- scratch (__device__ globals; no allocations) ----------------
__device__ int g_is64;
__device__ int g_deg_u[NUSER];
__device__ int g_deg_r[NREPO];
__device__ int g_rp_u[NUSER + 1];
__device__ int g_rp_r[NREPO + 1];
__device__ int g_fill_u[NUSER];
__device__ int g_fill_r[NREPO];
__device__ int g_adj_u[NEDGE];
__device__ int g_adj_r[NEDGE];
__device__ int g_bsum[2 * 64];
__device__ __align__(128) float g_mean_u[(size_t)NUSER * DD];
__device__ __align__(128) float g_mean_r[(size_t)NREPO * DD];
__device__ __align__(128) float g_user_h[(size_t)NUSER * DD];
__device__ __align__(128) float g_repo_h[(size_t)NREPO * DD];

// ---------------- edge dtype probe + accessors ----------------
__global__ void probe_kernel(const int* __restrict__ e32) {
    __shared__ int nonzero;
    if (threadIdx.x == 0) nonzero = 0;
    __syncthreads();
    if (e32[threadIdx.x * 2 + 1] != 0) atomicOr(&nonzero, 1);
    __syncthreads();
    if (threadIdx.x == 0) g_is64 = (nonzero ? 0 : 1);
}

__device__ __forceinline__ int edge_at(const void* edges, int row, int i, int is64) {
    if (is64) {
        long long v = ((const long long*)edges)[(size_t)row * NEDGE + i];
        return (int)v;
    }
    return ((const int*)edges)[(size_t)row * NEDGE + i];
}

__device__ __forceinline__ int clampi(int v, int hi) {
    return v < 0 ? 0 : (v >= hi ? hi - 1 : v);
}

// ---------------- CSR build ----------------
__global__ void zero_deg_kernel() {
    int i = blockIdx.x * blockDim.x + threadIdx.x;
    int stride = gridDim.x * blockDim.x;
    for (int j = i; j < NUSER; j += stride) g_deg_u[j] = 0;
    for (int j = i; j < NREPO; j += stride) g_deg_r[j] = 0;
}

__global__ void degree_kernel(const void* __restrict__ edges) {
    int is64 = g_is64;
    int stride = gridDim.x * blockDim.x;
    for (int i = blockIdx.x * blockDim.x + threadIdx.x; i < NEDGE; i += stride) {
        int u = clampi(edge_at(edges, 0, i, is64), NUSER);
        int r = clampi(edge_at(edges, 1, i, is64), NREPO);
        atomicAdd(&g_deg_u[u], 1);
        atomicAdd(&g_deg_r[r], 1);
    }
}

__global__ void scan1_kernel() {
    int side = blockIdx.y;
    int nb = side ? NB_R : NB_U;
    int b = blockIdx.x;
    if (b >= nb) return;
    int n = side ? NREPO : NUSER;
    const int* deg = side ? g_deg_r : g_deg_u;
    int* rp = side ? g_rp_r : g_rp_u;

    int tid = threadIdx.x;
    int lane = tid & 31, w = tid >> 5;
    int base = b * SCHUNK + tid * 4;

    int v[4];
    int t = 0;
#pragma unroll
    for (int j = 0; j < 4; j++) {
        int i = base + j;
        v[j] = (i < n) ? deg[i] : 0;
        t += v[j];
    }
    __shared__ int wsum[32];
    int inc = t;
#pragma unroll
    for (int o = 1; o < 32; o <<= 1) {
        int x = __shfl_up_sync(~0u, inc, o);
        if (lane >= o) inc += x;
    }
    if (lane == 31) wsum[w] = inc;
    __syncthreads();
    if (w == 0) {
        int s = wsum[lane];
#pragma unroll
        for (int o = 1; o < 32; o <<= 1) {
            int x = __shfl_up_sync(~0u, s, o);
            if (lane >= o) s += x;
        }
        wsum[lane] = s;
    }
    __syncthreads();
    int ex = inc - t + (w > 0 ? wsum[w - 1] : 0);
    int run = ex;
#pragma unroll
    for (int j = 0; j < 4; j++) {
        int i = base + j;
        if (i < n) rp[i] = run;
        run += v[j];
    }
    if (tid == 1023) g_bsum[side * 64 + b] = run;
}

__global__ void scan2_kernel() {
    int tid = threadIdx.x;
    if (tid < 2) {
        int nb = tid ? NB_R : NB_U;
        int* bs = g_bsum + tid * 64;
        int s = 0;
        for (int i = 0; i < nb; i++) { int x = bs[i]; bs[i] = s; s += x; }
    }
}

__global__ void scan3_kernel() {
    int side = blockIdx.y;
    int nb = side ? NB_R : NB_U;
    int b = blockIdx.x;
    if (b >= nb) return;
    int n = side ? NREPO : NUSER;
    int* rp = side ? g_rp_r : g_rp_u;
    int* fill = side ? g_fill_r : g_fill_u;
    int off = g_bsum[side * 64 + b];
    int base = b * SCHUNK + threadIdx.x * 4;
#pragma unroll
    for (int j = 0; j < 4; j++) {
        int i = base + j;
        if (i < n) {
            int x = rp[i] + off;
            rp[i] = x;
            fill[i] = x;
        }
    }
    if (b == 0 && threadIdx.x == 0) rp[n] = NEDGE;
}

__global__ void place_kernel(const void* __restrict__ edges) {
    int is64 = g_is64;
    int stride = gridDim.x * blockDim.x;
    for (int i = blockIdx.x * blockDim.x + threadIdx.x; i < NEDGE; i += stride) {
        int u = clampi(edge_at(edges, 0, i, is64), NUSER);
        int r = clampi(edge_at(edges, 1, i, is64), NREPO);
        g_adj_r[atomicAdd(&g_fill_r[r], 1)] = u;
        g_adj_u[atomicAdd(&g_fill_u[u], 1)] = r;
    }
}

// ---------------- dual gather-mean: one warp per destination row -------------
// covers rows [0, NREPO) -> repo destinations, [NREPO, NREPO+NUSER) -> user.
// layer==1: repo<-x_user, user<-x_repo; layer==2: repo<-g_user_h, user<-g_repo_h.
__global__ void gather_dual_kernel(const float* __restrict__ xu,
                                   const float* __restrict__ xr,
                                   int layer) {
    int gw = (blockIdx.x * blockDim.x + threadIdx.x) >> 5;
    int lane = threadIdx.x & 31;

    const float* src;
    float* dst;
    const int* rp;
    const int* adj;
    int row;
    if (gw < NREPO) {
        row = gw;
        src = (layer == 1) ? xu : g_user_h;
        dst = g_mean_r;
        rp = g_rp_r;
        adj = g_adj_r;
    } else {
        row = gw - NREPO;
        if (row >= NUSER) return;
        src = (layer == 1) ? xr : g_repo_h;
        dst = g_mean_u;
        rp = g_rp_u;
        adj = g_adj_u;
    }

    int beg = rp[row], end = rp[row + 1];
    float4 a0 = make_float4(0.f, 0.f, 0.f, 0.f);
    float4 a1 = a0, a2 = a0, a3 = a0;
    int j = beg;
    for (; j + 4 <= end; j += 4) {
        int n0 = adj[j], n1 = adj[j + 1], n2 = adj[j + 2], n3 = adj[j + 3];
        float4 v0 = ((const float4*)(src + (size_t)n0 * DD))[lane];
        float4 v1 = ((const float4*)(src + (size_t)n1 * DD))[lane];
        float4 v2 = ((const float4*)(src + (size_t)n2 * DD))[lane];
        float4 v3 = ((const float4*)(src + (size_t)n3 * DD))[lane];
        a0.x += v0.x; a0.y += v0.y; a0.z += v0.z; a0.w += v0.w;
        a1.x += v1.x; a1.y += v1.y; a1.z += v1.z; a1.w += v1.w;
        a2.x += v2.x; a2.y += v2.y; a2.z += v2.z; a2.w += v2.w;
        a3.x += v3.x; a3.y += v3.y; a3.z += v3.z; a3.w += v3.w;
    }
    for (; j < end; j++) {
        float4 v = ((const float4*)(src + (size_t)adj[j] * DD))[lane];
        a0.x += v.x; a0.y += v.y; a0.z += v.z; a0.w += v.w;
    }
    float4 s;
    s.x = (a0.x + a1.x) + (a2.x + a3.x);
    s.y = (a0.y + a1.y) + (a2.y + a3.y);
    s.z = (a0.z + a1.z) + (a2.z + a3.z);
    s.w = (a0.w + a1.w) + (a2.w + a3.w);
    float sc = 1.f / (float)max(end - beg, 1);
    s.x *= sc; s.y *= sc; s.z *= sc; s.w *= sc;
    ((float4*)(dst + (size_t)row * DD))[lane] = s;
}

// ---------------- fast fused SAGE GEMM: tf32 mma.sync, BM=128, K=256 --------
__device__ __forceinline__ unsigned f2tf32(float f) {
    unsigned u;
    asm("cvt.rna.tf32.f32 %0, %1;" : "=r"(u) : "f"(f));
    return u;
}

__device__ __forceinline__ void mma_tf32(float c[4], const unsigned a[4], const unsigned b[2]) {
    asm volatile(
        "mma.sync.aligned.m16n8k8.row.col.f32.tf32.tf32.f32 "
        "{%0,%1,%2,%3}, {%4,%5,%6,%7}, {%8,%9}, {%0,%1,%2,%3};"
        : "+f"(c[0]), "+f"(c[1]), "+f"(c[2]), "+f"(c[3])
        : "r"(a[0]), "r"(a[1]), "r"(a[2]), "r"(a[3]), "r"(b[0]), "r"(b[1]));
}

#define WPITCH 136   // smem pitch for W rows
#define APAD   20    // smem pitch for A rows

template <bool RELU>
__global__ void __launch_bounds__(256, 1)
gemm_fused(int meanRepo,                       // 1 -> g_mean_r, 0 -> g_mean_u
           const float* __restrict__ ext_x,    // self features if xSel==0
           int xSel,                           // 0 ext, 1 g_user_h, 2 g_repo_h
           const float* __restrict__ Wl,
           const float* __restrict__ Wr,
           const float* __restrict__ bias,
           float* __restrict__ ext_out,
           int outSel,                         // 0 ext, 1 g_user_h, 2 g_repo_h
           int rows) {
    extern __shared__ float sm[];
    float* Wsh = sm;                  // 256 x WPITCH
    float* Ash = sm + 256 * WPITCH;   // 2 x 128 x APAD

    const float* Abuf = meanRepo ? g_mean_r : g_mean_u;
    const float* X = (xSel == 0) ? ext_x : (xSel == 1 ? g_user_h : g_repo_h);
    float* out = (outSel == 0) ? ext_out : (outSel == 1 ? g_user_h : g_repo_h);

    const int tid = threadIdx.x;
    const int lane = tid & 31;
    const int warp = tid >> 5;
    const int wm = (warp >> 2) * 64;
    const int wn = (warp & 3) * 32;
    const int blockRow = blockIdx.x * 128;

    {   // W = [Wl; Wr] -> smem (tf32-rounded once)
        const float* src = (tid < 128) ? (Wl + (size_t)tid * 128)
                                       : (Wr + (size_t)(tid - 128) * 128);
        float* dst = Wsh + tid * WPITCH;
#pragma unroll
        for (int c = 0; c < 128; c += 4) {
            float4 v = *(const float4*)(src + c);
            dst[c + 0] = __uint_as_float(f2tf32(v.x));
            dst[c + 1] = __uint_as_float(f2tf32(v.y));
            dst[c + 2] = __uint_as_float(f2tf32(v.z));
            dst[c + 3] = __uint_as_float(f2tf32(v.w));
        }
    }

    const int lr = tid >> 2;          // 0..63 (rows lr and lr+64)
    const int c4 = (tid & 3) * 4;     // 0,4,8,12 within 16-wide K chunk
    const int cr0 = min(blockRow + lr, rows - 1);
    const int cr1 = min(blockRow + lr + 64, rows - 1);

    float cfr[4][4][4];
#pragma unroll
    for (int f = 0; f < 4; f++)
#pragma unroll
        for (int g = 0; g < 4; g++)
#pragma unroll
            for (int k = 0; k < 4; k++) cfr[f][g][k] = 0.f;

    auto loadch = [&](int ch, float4& p0, float4& p1) {
        const float* B0 = (ch < 8) ? Abuf : X;
        int cc = (ch < 8) ? ch * 16 + c4 : (ch - 8) * 16 + c4;
        p0 = *(const float4*)(B0 + (size_t)cr0 * DD + cc);
        p1 = *(const float4*)(B0 + (size_t)cr1 * DD + cc);
    };
    auto storech = [&](int buf, float4 p0, float4 p1) {
        float* base = Ash + buf * (128 * APAD);
        float4 t0, t1;
        t0.x = __uint_as_float(f2tf32(p0.x)); t0.y = __uint_as_float(f2tf32(p0.y));
        t0.z = __uint_as_float(f2tf32(p0.z)); t0.w = __uint_as_float(f2tf32(p0.w));
        t1.x = __uint_as_float(f2tf32(p1.x)); t1.y = __uint_as_float(f2tf32(p1.y));
        t1.z = __uint_as_float(f2tf32(p1.z)); t1.w = __uint_as_float(f2tf32(p1.w));
        *(float4*)(base + (size_t)lr * APAD + c4) = t0;
        *(float4*)(base + (size_t)(lr + 64) * APAD + c4) = t1;
    };

    float4 p0, p1;
    loadch(0, p0, p1);
    storech(0, p0, p1);
    __syncthreads();

#pragma unroll 1
    for (int ch = 0; ch < 16; ch++) {
        float4 q0, q1;
        if (ch < 15) loadch(ch + 1, q0, q1);   // overlap gmem with mma

        const float* Ab = Ash + (ch & 1) * (128 * APAD);
        const float* Wb = Wsh + (size_t)ch * 16 * WPITCH;

#pragma unroll
        for (int kk = 0; kk < 2; kk++) {
            unsigned a[4][4], b[4][2];
            const int ar = wm + (lane >> 2);
            const int ak = kk * 8 + (lane & 3);
#pragma unroll
            for (int f = 0; f < 4; f++) {
                const float* ab = Ab + (size_t)(ar + f * 16) * APAD + ak;
                a[f][0] = __float_as_uint(ab[0]);
                a[f][1] = __float_as_uint(ab[8 * APAD]);
                a[f][2] = __float_as_uint(ab[4]);
                a[f][3] = __float_as_uint(ab[8 * APAD + 4]);
            }
            const int bk = kk * 8 + (lane & 3);
            const int bn = wn + (lane >> 2);
#pragma unroll
            for (int g = 0; g < 4; g++) {
                const float* bb = Wb + (size_t)bk * WPITCH + bn + g * 8;
                b[g][0] = __float_as_uint(bb[0]);
                b[g][1] = __float_as_uint(bb[4 * WPITCH]);
            }
#pragma unroll
            for (int f = 0; f < 4; f++)
#pragma unroll
                for (int g = 0; g < 4; g++) mma_tf32(cfr[f][g], a[f], b[g]);
        }

        if (ch < 15) storech((ch + 1) & 1, q0, q1);
        __syncthreads();
    }

    // epilogue: bias (+relu), guarded writes
#pragma unroll
    for (int f = 0; f < 4; f++) {
        int r0 = blockRow + wm + f * 16 + (lane >> 2);
#pragma unroll
        for (int g = 0; g < 4; g++) {
            int c = wn + g * 8 + (lane & 3) * 2;
            float b0 = bias[c], b1 = bias[c + 1];
            if (r0 < rows) {
                float v0 = cfr[f][g][0] + b0;
                float v1 = cfr[f][g][1] + b1;
                if (RELU) { v0 = fmaxf(v0, 0.f); v1 = fmaxf(v1, 0.f); }
                out[(size_t)r0 * DD + c] = v0;
                out[(size_t)r0 * DD + c + 1] = v1;
            }
            if (r0 + 8 < rows) {
                float v2 = cfr[f][g][2] + b0;
                float v3 = cfr[f][g][3] + b1;
                if (RELU) { v2 = fmaxf(v2, 0.f); v3 = fmaxf(v3, 0.f); }
                out[(size_t)(r0 + 8) * DD + c] = v2;
                out[(size_t)(r0 + 8) * DD + c + 1] = v3;
            }
        }
    }
}

// ---------------- launch ----------------
extern "C" void kernel_launch(void* const* d_in, const int* in_sizes, int n_in,
                              void* d_out, int out_size) {
    const float* x_user = (const float*)d_in[0];
    const float* x_repo = (const float*)d_in[1];
    const void* edges = d_in[2];
    const float* Wl1s = (const float*)d_in[3];
    const float* bl1s = (const float*)d_in[4];
    const float* Wr1s = (const float*)d_in[5];
    const float* Wl1r = (const float*)d_in[6];
    const float* bl1r = (const float*)d_in[7];
    const float* Wr1r = (const float*)d_in[8];
    const float* Wl2s = (const float*)d_in[9];
    const float* bl2s = (const float*)d_in[10];
    const float* Wr2s = (const float*)d_in[11];
    const float* Wl2r = (const float*)d_in[12];
    const float* bl2r = (const float*)d_in[13];
    const float* Wr2r = (const float*)d_in[14];

    float* out_user = (float*)d_out;
    float* out_repo = out_user + (size_t)NUSER * DD;

    const int smem = (256 * WPITCH + 2 * 128 * APAD) * sizeof(float);
    static int attr_done = 0;
    if (!attr_done) {
        cudaFuncSetAttribute(gemm_fused<true>, cudaFuncAttributeMaxDynamicSharedMemorySize, smem);
        cudaFuncSetAttribute(gemm_fused<false>, cudaFuncAttributeMaxDynamicSharedMemorySize, smem);
        attr_done = 1;
    }

    // ---- edge dtype probe + CSR build (once; reused by both layers) ----
    probe_kernel<<<1, 256>>>((const int*)edges);
    zero_deg_kernel<<<512, 512>>>();
    degree_kernel<<<2048, 256>>>(edges);
    dim3 gs(NB_U, 2);
    scan1_kernel<<<gs, 1024>>>();
    scan2_kernel<<<1, 32>>>();
    scan3_kernel<<<gs, 1024>>>();
    place_kernel<<<2048, 256>>>(edges);

    const int gwarps = NREPO + NUSER;
    const int gblocks = (gwarps * 32 + 255) / 256;

    // ---- layer 1 ----
    gather_dual_kernel<<<gblocks, 256>>>(x_user, x_repo, 1);
    gemm_fused<true><<<(NREPO + 127) / 128, 256, smem>>>(
        1, x_repo, 0, Wl1s, Wr1s, bl1s, nullptr, 2, NREPO);
    gemm_fused<true><<<(NUSER + 127) / 128, 256, smem>>>(
        0, x_user, 0, Wl1r, Wr1r, bl1r, nullptr, 1, NUSER);

    // ---- layer 2 ----
    gather_dual_kernel<<<gblocks, 256>>>(nullptr, nullptr, 2);
    gemm_fused<false><<<(NREPO + 127) / 128, 256, smem>>>(
        1, nullptr, 2, Wl2s, Wr2s, bl2s, out_repo, 0, NREPO);
    gemm_fused<false><<<(NUSER + 127) / 128, 256, smem>>>(
        0, nullptr, 1, Wl2r, Wr2r, bl2r, out_user, 0, NUSER);
}

// round 9
// speedup vs baseline: 1.2487x; 1.0054x over previous
#include <cuda_runtime.h>
#include <cuda_fp16.h>
#include <cstdint>

#define NUSER 200000
#define NREPO 100000
#define NEDGE 1500000
#define DD    128
#define SCHUNK 4096
#define NB_U ((NUSER + SCHUNK - 1) / SCHUNK)   // 49
#define NB_R ((NREPO + SCHUNK - 1) / SCHUNK)   // 25

// ---------------- scratch (__device__ globals; no allocations) ----------------
__device__ int g_is64;
__device__ int g_deg_u[NUSER];
__device__ int g_deg_r[NREPO];
__device__ int g_rp_u[NUSER + 1];
__device__ int g_rp_r[NREPO + 1];
__device__ int g_fill_u[NUSER];
__device__ int g_fill_r[NREPO];
__device__ int g_adj_u[NEDGE];
__device__ int g_adj_r[NEDGE];
__device__ int g_bsum[2 * 64];
__device__ __align__(128) float g_mean_u[(size_t)NUSER * DD];
__device__ __align__(128) float g_mean_r[(size_t)NREPO * DD];
__device__ __align__(128) float g_user_h[(size_t)NUSER * DD];
__device__ __align__(128) float g_repo_h[(size_t)NREPO * DD];
// fp16 gather sources: layer1 = inputs, layer2 = hidden states
__device__ __align__(128) __half g_x16_u[(size_t)NUSER * DD];
__device__ __align__(128) __half g_x16_r[(size_t)NREPO * DD];
__device__ __align__(128) __half g_h16_u[(size_t)NUSER * DD];
__device__ __align__(128) __half g_h16_r[(size_t)NREPO * DD];

// ---------------- edge dtype probe + accessors ----------------
__global__ void probe_kernel(const int* __restrict__ e32) {
    __shared__ int nonzero;
    if (threadIdx.x == 0) nonzero = 0;
    __syncthreads();
    if (e32[threadIdx.x * 2 + 1] != 0) atomicOr(&nonzero, 1);
    __syncthreads();
    if (threadIdx.x == 0) g_is64 = (nonzero ? 0 : 1);
}

__device__ __forceinline__ int edge_at(const void* edges, int row, int i, int is64) {
    if (is64) {
        long long v = ((const long long*)edges)[(size_t)row * NEDGE + i];
        return (int)v;
    }
    return ((const int*)edges)[(size_t)row * NEDGE + i];
}

__device__ __forceinline__ int clampi(int v, int hi) {
    return v < 0 ? 0 : (v >= hi ? hi - 1 : v);
}

// ---------------- fp32 -> fp16 conversion (both inputs in one kernel) -------
__global__ void tohalf_kernel(const float* __restrict__ xu,
                              const float* __restrict__ xr) {
    const size_t nu4 = (size_t)NUSER * DD / 4;
    const size_t nr4 = (size_t)NREPO * DD / 4;
    size_t stride = (size_t)gridDim.x * blockDim.x;
    for (size_t i = (size_t)blockIdx.x * blockDim.x + threadIdx.x;
         i < nu4 + nr4; i += stride) {
        const float4* src;
        uint2* dst;
        size_t j;
        if (i < nu4) { src = (const float4*)xu; dst = (uint2*)g_x16_u; j = i; }
        else         { src = (const float4*)xr; dst = (uint2*)g_x16_r; j = i - nu4; }
        float4 v = src[j];
        __half2 h0 = __floats2half2_rn(v.x, v.y);
        __half2 h1 = __floats2half2_rn(v.z, v.w);
        uint2 o;
        o.x = *(unsigned*)&h0;
        o.y = *(unsigned*)&h1;
        dst[j] = o;
    }
}

// ---------------- CSR build ----------------
__global__ void zero_deg_kernel() {
    int i = blockIdx.x * blockDim.x + threadIdx.x;
    int stride = gridDim.x * blockDim.x;
    for (int j = i; j < NUSER; j += stride) g_deg_u[j] = 0;
    for (int j = i; j < NREPO; j += stride) g_deg_r[j] = 0;
}

__global__ void degree_kernel(const void* __restrict__ edges) {
    int is64 = g_is64;
    int stride = gridDim.x * blockDim.x;
    for (int i = blockIdx.x * blockDim.x + threadIdx.x; i < NEDGE; i += stride) {
        int u = clampi(edge_at(edges, 0, i, is64), NUSER);
        int r = clampi(edge_at(edges, 1, i, is64), NREPO);
        atomicAdd(&g_deg_u[u], 1);
        atomicAdd(&g_deg_r[r], 1);
    }
}

__global__ void scan1_kernel() {
    int side = blockIdx.y;
    int nb = side ? NB_R : NB_U;
    int b = blockIdx.x;
    if (b >= nb) return;
    int n = side ? NREPO : NUSER;
    const int* deg = side ? g_deg_r : g_deg_u;
    int* rp = side ? g_rp_r : g_rp_u;

    int tid = threadIdx.x;
    int lane = tid & 31, w = tid >> 5;
    int base = b * SCHUNK + tid * 4;

    int v[4];
    int t = 0;
#pragma unroll
    for (int j = 0; j < 4; j++) {
        int i = base + j;
        v[j] = (i < n) ? deg[i] : 0;
        t += v[j];
    }
    __shared__ int wsum[32];
    int inc = t;
#pragma unroll
    for (int o = 1; o < 32; o <<= 1) {
        int x = __shfl_up_sync(~0u, inc, o);
        if (lane >= o) inc += x;
    }
    if (lane == 31) wsum[w] = inc;
    __syncthreads();
    if (w == 0) {
        int s = wsum[lane];
#pragma unroll
        for (int o = 1; o < 32; o <<= 1) {
            int x = __shfl_up_sync(~0u, s, o);
            if (lane >= o) s += x;
        }
        wsum[lane] = s;
    }
    __syncthreads();
    int ex = inc - t + (w > 0 ? wsum[w - 1] : 0);
    int run = ex;
#pragma unroll
    for (int j = 0; j < 4; j++) {
        int i = base + j;
        if (i < n) rp[i] = run;
        run += v[j];
    }
    if (tid == 1023) g_bsum[side * 64 + b] = run;
}

__global__ void scan2_kernel() {
    int tid = threadIdx.x;
    if (tid < 2) {
        int nb = tid ? NB_R : NB_U;
        int* bs = g_bsum + tid * 64;
        int s = 0;
        for (int i = 0; i < nb; i++) { int x = bs[i]; bs[i] = s; s += x; }
    }
}

__global__ void scan3_kernel() {
    int side = blockIdx.y;
    int nb = side ? NB_R : NB_U;
    int b = blockIdx.x;
    if (b >= nb) return;
    int n = side ? NREPO : NUSER;
    int* rp = side ? g_rp_r : g_rp_u;
    int* fill = side ? g_fill_r : g_fill_u;
    int off = g_bsum[side * 64 + b];
    int base = b * SCHUNK + threadIdx.x * 4;
#pragma unroll
    for (int j = 0; j < 4; j++) {
        int i = base + j;
        if (i < n) {
            int x = rp[i] + off;
            rp[i] = x;
            fill[i] = x;
        }
    }
    if (b == 0 && threadIdx.x == 0) rp[n] = NEDGE;
}

__global__ void place_kernel(const void* __restrict__ edges) {
    int is64 = g_is64;
    int stride = gridDim.x * blockDim.x;
    for (int i = blockIdx.x * blockDim.x + threadIdx.x; i < NEDGE; i += stride) {
        int u = clampi(edge_at(edges, 0, i, is64), NUSER);
        int r = clampi(edge_at(edges, 1, i, is64), NREPO);
        g_adj_r[atomicAdd(&g_fill_r[r], 1)] = u;
        g_adj_u[atomicAdd(&g_fill_u[u], 1)] = r;
    }
}

// ---------------- dual gather-mean (fp16 src): one warp per dst row ---------
__global__ void gather_dual_kernel(int layer) {
    int gw = (blockIdx.x * blockDim.x + threadIdx.x) >> 5;
    int lane = threadIdx.x & 31;

    const __half* src;
    float* dst;
    const int* rp;
    const int* adj;
    int row;
    if (gw < NREPO) {
        row = gw;
        src = (layer == 1) ? g_x16_u : g_h16_u;
        dst = g_mean_r;
        rp = g_rp_r;
        adj = g_adj_r;
    } else {
        row = gw - NREPO;
        if (row >= NUSER) return;
        src = (layer == 1) ? g_x16_r : g_h16_r;
        dst = g_mean_u;
        rp = g_rp_u;
        adj = g_adj_u;
    }

    int beg = rp[row], end = rp[row + 1];
    float4 a0 = make_float4(0.f, 0.f, 0.f, 0.f);
    float4 a1 = a0, a2 = a0, a3 = a0;

    int j = beg;
    for (; j + 4 <= end; j += 4) {
        int n0 = adj[j], n1 = adj[j + 1], n2 = adj[j + 2], n3 = adj[j + 3];
        uint2 w0 = ((const uint2*)(src + (size_t)n0 * DD))[lane];
        uint2 w1 = ((const uint2*)(src + (size_t)n1 * DD))[lane];
        uint2 w2 = ((const uint2*)(src + (size_t)n2 * DD))[lane];
        uint2 w3 = ((const uint2*)(src + (size_t)n3 * DD))[lane];
        float2 f;
        f = __half22float2(*(__half2*)&w0.x); a0.x += f.x; a0.y += f.y;
        f = __half22float2(*(__half2*)&w0.y); a0.z += f.x; a0.w += f.y;
        f = __half22float2(*(__half2*)&w1.x); a1.x += f.x; a1.y += f.y;
        f = __half22float2(*(__half2*)&w1.y); a1.z += f.x; a1.w += f.y;
        f = __half22float2(*(__half2*)&w2.x); a2.x += f.x; a2.y += f.y;
        f = __half22float2(*(__half2*)&w2.y); a2.z += f.x; a2.w += f.y;
        f = __half22float2(*(__half2*)&w3.x); a3.x += f.x; a3.y += f.y;
        f = __half22float2(*(__half2*)&w3.y); a3.z += f.x; a3.w += f.y;
    }
    for (; j < end; j++) {
        uint2 w = ((const uint2*)(src + (size_t)adj[j] * DD))[lane];
        float2 f;
        f = __half22float2(*(__half2*)&w.x); a0.x += f.x; a0.y += f.y;
        f = __half22float2(*(__half2*)&w.y); a0.z += f.x; a0.w += f.y;
    }
    float4 s;
    s.x = (a0.x + a1.x) + (a2.x + a3.x);
    s.y = (a0.y + a1.y) + (a2.y + a3.y);
    s.z = (a0.z + a1.z) + (a2.z + a3.z);
    s.w = (a0.w + a1.w) + (a2.w + a3.w);
    float sc = 1.f / (float)max(end - beg, 1);
    s.x *= sc; s.y *= sc; s.z *= sc; s.w *= sc;
    ((float4*)(dst + (size_t)row * DD))[lane] = s;
}

// ---------------- fast fused SAGE GEMM: tf32 mma.sync, BM=128, K=256 --------
__device__ __forceinline__ unsigned f2tf32(float f) {
    unsigned u;
    asm("cvt.rna.tf32.f32 %0, %1;" : "=r"(u) : "f"(f));
    return u;
}

__device__ __forceinline__ void mma_tf32(float c[4], const unsigned a[4], const unsigned b[2]) {
    asm volatile(
        "mma.sync.aligned.m16n8k8.row.col.f32.tf32.tf32.f32 "
        "{%0,%1,%2,%3}, {%4,%5,%6,%7}, {%8,%9}, {%0,%1,%2,%3};"
        : "+f"(c[0]), "+f"(c[1]), "+f"(c[2]), "+f"(c[3])
        : "r"(a[0]), "r"(a[1]), "r"(a[2]), "r"(a[3]), "r"(b[0]), "r"(b[1]));
}

#define WPITCH 136
#define APAD   20

template <bool RELU>
__global__ void __launch_bounds__(256, 1)
gemm_fused(int meanRepo,
           const float* __restrict__ ext_x,
           int xSel,                           // 0 ext, 1 g_user_h, 2 g_repo_h
           const float* __restrict__ Wl,
           const float* __restrict__ Wr,
           const float* __restrict__ bias,
           float* __restrict__ ext_out,
           int outSel,                         // 0 ext, 1 g_user_h, 2 g_repo_h
           int rows) {
    extern __shared__ float sm[];
    float* Wsh = sm;                  // 256 x WPITCH
    float* Ash = sm + 256 * WPITCH;   // 2 x 128 x APAD

    const float* Abuf = meanRepo ? g_mean_r : g_mean_u;
    const float* X = (xSel == 0) ? ext_x : (xSel == 1 ? g_user_h : g_repo_h);
    float* out = (outSel == 0) ? ext_out : (outSel == 1 ? g_user_h : g_repo_h);
    __half* out16 = (outSel == 1) ? g_h16_u : (outSel == 2 ? g_h16_r : nullptr);

    const int tid = threadIdx.x;
    const int lane = tid & 31;
    const int warp = tid >> 5;
    const int wm = (warp >> 2) * 64;
    const int wn = (warp & 3) * 32;
    const int blockRow = blockIdx.x * 128;

    {   // W = [Wl; Wr] -> smem (tf32-rounded once)
        const float* src = (tid < 128) ? (Wl + (size_t)tid * 128)
                                       : (Wr + (size_t)(tid - 128) * 128);
        float* dst = Wsh + tid * WPITCH;
#pragma unroll
        for (int c = 0; c < 128; c += 4) {
            float4 v = *(const float4*)(src + c);
            dst[c + 0] = __uint_as_float(f2tf32(v.x));
            dst[c + 1] = __uint_as_float(f2tf32(v.y));
            dst[c + 2] = __uint_as_float(f2tf32(v.z));
            dst[c + 3] = __uint_as_float(f2tf32(v.w));
        }
    }

    const int lr = tid >> 2;
    const int c4 = (tid & 3) * 4;
    const int cr0 = min(blockRow + lr, rows - 1);
    const int cr1 = min(blockRow + lr + 64, rows - 1);

    float cfr[4][4][4];
#pragma unroll
    for (int f = 0; f < 4; f++)
#pragma unroll
        for (int g = 0; g < 4; g++)
#pragma unroll
            for (int k = 0; k < 4; k++) cfr[f][g][k] = 0.f;

    auto loadch = [&](int ch, float4& p0, float4& p1) {
        const float* B0 = (ch < 8) ? Abuf : X;
        int cc = (ch < 8) ? ch * 16 + c4 : (ch - 8) * 16 + c4;
        p0 = *(const float4*)(B0 + (size_t)cr0 * DD + cc);
        p1 = *(const float4*)(B0 + (size_t)cr1 * DD + cc);
    };
    auto storech = [&](int buf, float4 p0, float4 p1) {
        float* base = Ash + buf * (128 * APAD);
        float4 t0, t1;
        t0.x = __uint_as_float(f2tf32(p0.x)); t0.y = __uint_as_float(f2tf32(p0.y));
        t0.z = __uint_as_float(f2tf32(p0.z)); t0.w = __uint_as_float(f2tf32(p0.w));
        t1.x = __uint_as_float(f2tf32(p1.x)); t1.y = __uint_as_float(f2tf32(p1.y));
        t1.z = __uint_as_float(f2tf32(p1.z)); t1.w = __uint_as_float(f2tf32(p1.w));
        *(float4*)(base + (size_t)lr * APAD + c4) = t0;
        *(float4*)(base + (size_t)(lr + 64) * APAD + c4) = t1;
    };

    float4 p0, p1;
    loadch(0, p0, p1);
    storech(0, p0, p1);
    __syncthreads();

#pragma unroll 1
    for (int ch = 0; ch < 16; ch++) {
        float4 q0, q1;
        if (ch < 15) loadch(ch + 1, q0, q1);

        const float* Ab = Ash + (ch & 1) * (128 * APAD);
        const float* Wb = Wsh + (size_t)ch * 16 * WPITCH;

#pragma unroll
        for (int kk = 0; kk < 2; kk++) {
            unsigned a[4][4], b[4][2];
            const int ar = wm + (lane >> 2);
            const int ak = kk * 8 + (lane & 3);
#pragma unroll
            for (int f = 0; f < 4; f++) {
                const float* ab = Ab + (size_t)(ar + f * 16) * APAD + ak;
                a[f][0] = __float_as_uint(ab[0]);
                a[f][1] = __float_as_uint(ab[8 * APAD]);
                a[f][2] = __float_as_uint(ab[4]);
                a[f][3] = __float_as_uint(ab[8 * APAD + 4]);
            }
            const int bk = kk * 8 + (lane & 3);
            const int bn = wn + (lane >> 2);
#pragma unroll
            for (int g = 0; g < 4; g++) {
                const float* bb = Wb + (size_t)bk * WPITCH + bn + g * 8;
                b[g][0] = __float_as_uint(bb[0]);
                b[g][1] = __float_as_uint(bb[4 * WPITCH]);
            }
#pragma unroll
            for (int f = 0; f < 4; f++)
#pragma unroll
                for (int g = 0; g < 4; g++) mma_tf32(cfr[f][g], a[f], b[g]);
        }

        if (ch < 15) storech((ch + 1) & 1, q0, q1);
        __syncthreads();
    }

    // epilogue: bias (+relu), fp32 write + optional fp16 shadow write
#pragma unroll
    for (int f = 0; f < 4; f++) {
        int r0 = blockRow + wm + f * 16 + (lane >> 2);
#pragma unroll
        for (int g = 0; g < 4; g++) {
            int c = wn + g * 8 + (lane & 3) * 2;
            float b0 = bias[c], b1 = bias[c + 1];
            if (r0 < rows) {
                float v0 = cfr[f][g][0] + b0;
                float v1 = cfr[f][g][1] + b1;
                if (RELU) { v0 = fmaxf(v0, 0.f); v1 = fmaxf(v1, 0.f); }
                out[(size_t)r0 * DD + c] = v0;
                out[(size_t)r0 * DD + c + 1] = v1;
                if (out16)
                    *(__half2*)(out16 + (size_t)r0 * DD + c) =
                        __floats2half2_rn(v0, v1);
            }
            if (r0 + 8 < rows) {
                float v2 = cfr[f][g][2] + b0;
                float v3 = cfr[f][g][3] + b1;
                if (RELU) { v2 = fmaxf(v2, 0.f); v3 = fmaxf(v3, 0.f); }
                out[(size_t)(r0 + 8) * DD + c] = v2;
                out[(size_t)(r0 + 8) * DD + c + 1] = v3;
                if (out16)
                    *(__half2*)(out16 + (size_t)(r0 + 8) * DD + c) =
                        __floats2half2_rn(v2, v3);
            }
        }
    }
}

// ---------------- launch ----------------
extern "C" void kernel_launch(void* const* d_in, const int* in_sizes, int n_in,
                              void* d_out, int out_size) {
    const float* x_user = (const float*)d_in[0];
    const float* x_repo = (const float*)d_in[1];
    const void* edges = d_in[2];
    const float* Wl1s = (const float*)d_in[3];
    const float* bl1s = (const float*)d_in[4];
    const float* Wr1s = (const float*)d_in[5];
    const float* Wl1r = (const float*)d_in[6];
    const float* bl1r = (const float*)d_in[7];
    const float* Wr1r = (const float*)d_in[8];
    const float* Wl2s = (const float*)d_in[9];
    const float* bl2s = (const float*)d_in[10];
    const float* Wr2s = (const float*)d_in[11];
    const float* Wl2r = (const float*)d_in[12];
    const float* bl2r = (const float*)d_in[13];
    const float* Wr2r = (const float*)d_in[14];

    float* out_user = (float*)d_out;
    float* out_repo = out_user + (size_t)NUSER * DD;

    const int smem = (256 * WPITCH + 2 * 128 * APAD) * sizeof(float);
    cudaFuncSetAttribute(gemm_fused<true>, cudaFuncAttributeMaxDynamicSharedMemorySize, smem);
    cudaFuncSetAttribute(gemm_fused<false>, cudaFuncAttributeMaxDynamicSharedMemorySize, smem);

    // ---- probe + fp16 copies + CSR build (once; reused by both layers) ----
    probe_kernel<<<1, 256>>>((const int*)edges);
    tohalf_kernel<<<2048, 256>>>(x_user, x_repo);
    zero_deg_kernel<<<512, 512>>>();
    degree_kernel<<<2048, 256>>>(edges);
    dim3 gs(NB_U, 2);
    scan1_kernel<<<gs, 1024>>>();
    scan2_kernel<<<1, 32>>>();
    scan3_kernel<<<gs, 1024>>>();
    place_kernel<<<2048, 256>>>(edges);

    const int gwarps = NREPO + NUSER;
    const int gblocks = (gwarps * 32 + 255) / 256;

    // ---- layer 1 ----
    gather_dual_kernel<<<gblocks, 256>>>(1);
    gemm_fused<true><<<(NREPO + 127) / 128, 256, smem>>>(
        1, x_repo, 0, Wl1s, Wr1s, bl1s, nullptr, 2, NREPO);
    gemm_fused<true><<<(NUSER + 127) / 128, 256, smem>>>(
        0, x_user, 0, Wl1r, Wr1r, bl1r, nullptr, 1, NUSER);

    // ---- layer 2 ----
    gather_dual_kernel<<<gblocks, 256>>>(2);
    gemm_fused<false><<<(NREPO + 127) / 128, 256, smem>>>(
        1, nullptr, 2, Wl2s, Wr2s, bl2s, out_repo, 0, NREPO);
    gemm_fused<false><<<(NUSER + 127) / 128, 256, smem>>>(
        0, nullptr, 1, Wl2r, Wr2r, bl2r, out_user, 0, NUSER);
}

// round 13
// speedup vs baseline: 1.4209x; 1.1379x over previous
#include <cuda_runtime.h>
#include <cuda_fp16.h>
#include <cstdint>

#define NUSER 200000
#define NREPO 100000
#define NEDGE 1500000
#define DD    128
#define SCHUNK 4096
#define NB_U ((NUSER + SCHUNK - 1) / SCHUNK)   // 49
#define NB_R ((NREPO + SCHUNK - 1) / SCHUNK)   // 25

// ---------------- scratch (__device__ globals; no allocations) ----------------
__device__ int g_is64;
__device__ int g_deg_u[NUSER];
__device__ int g_deg_r[NREPO];
__device__ int g_rp_u[NUSER + 1];
__device__ int g_rp_r[NREPO + 1];
__device__ int g_fill_u[NUSER];
__device__ int g_fill_r[NREPO];
__device__ int g_adj_u[NEDGE];
__device__ int g_adj_r[NEDGE];
__device__ int g_bsum[2 * 64];
// fp16 node features / hidden / means
__device__ __align__(128) __half g_x16_u[(size_t)NUSER * DD];
__device__ __align__(128) __half g_x16_r[(size_t)NREPO * DD];
__device__ __align__(128) __half g_h16_u[(size_t)NUSER * DD];
__device__ __align__(128) __half g_h16_r[(size_t)NREPO * DD];
__device__ __align__(128) __half g_m16_u[(size_t)NUSER * DD];
__device__ __align__(128) __half g_m16_r[(size_t)NREPO * DD];
// fp16 weights, transposed: [pair][n=128][k=256], k = [Wl rows | Wr rows]
__device__ __align__(128) __half g_w16[4 * 128 * 256];

// ---------------- edge dtype probe + accessors ----------------
__global__ void probe_kernel(const int* __restrict__ e32) {
    __shared__ int nonzero;
    if (threadIdx.x == 0) nonzero = 0;
    __syncthreads();
    if (e32[threadIdx.x * 2 + 1] != 0) atomicOr(&nonzero, 1);
    __syncthreads();
    if (threadIdx.x == 0) g_is64 = (nonzero ? 0 : 1);
}

__device__ __forceinline__ int edge_at(const void* edges, int row, int i, int is64) {
    if (is64) {
        long long v = ((const long long*)edges)[(size_t)row * NEDGE + i];
        return (int)v;
    }
    return ((const int*)edges)[(size_t)row * NEDGE + i];
}

__device__ __forceinline__ int clampi(int v, int hi) {
    return v < 0 ? 0 : (v >= hi ? hi - 1 : v);
}

// ---------------- fp32 -> fp16 conversion of inputs ----------------
__global__ void tohalf_kernel(const float* __restrict__ xu,
                              const float* __restrict__ xr) {
    const size_t nu4 = (size_t)NUSER * DD / 4;
    const size_t nr4 = (size_t)NREPO * DD / 4;
    size_t stride = (size_t)gridDim.x * blockDim.x;
    for (size_t i = (size_t)blockIdx.x * blockDim.x + threadIdx.x;
         i < nu4 + nr4; i += stride) {
        const float4* src;
        uint2* dst;
        size_t j;
        if (i < nu4) { src = (const float4*)xu; dst = (uint2*)g_x16_u; j = i; }
        else         { src = (const float4*)xr; dst = (uint2*)g_x16_r; j = i - nu4; }
        float4 v = src[j];
        __half2 h0 = __floats2half2_rn(v.x, v.y);
        __half2 h1 = __floats2half2_rn(v.z, v.w);
        uint2 o;
        o.x = *(unsigned*)&h0;
        o.y = *(unsigned*)&h1;
        dst[j] = o;
    }
}

// ---------------- weight prep: fp32 [k][n] pairs -> fp16 [n][k] ----------------
__global__ void wprep_kernel(const float* __restrict__ Wl0, const float* __restrict__ Wr0,
                             const float* __restrict__ Wl1, const float* __restrict__ Wr1,
                             const float* __restrict__ Wl2, const float* __restrict__ Wr2,
                             const float* __restrict__ Wl3, const float* __restrict__ Wr3) {
    int idx = blockIdx.x * blockDim.x + threadIdx.x;  // 4*32*128 = 16384 threads
    if (idx >= 4 * 32 * 128) return;
    int n = idx & 127;
    int kc = ((idx >> 7) & 31) * 8;
    int pair = idx >> 12;
    const float* Wl = (pair == 0) ? Wl0 : (pair == 1) ? Wl1 : (pair == 2) ? Wl2 : Wl3;
    const float* Wr = (pair == 0) ? Wr0 : (pair == 1) ? Wr1 : (pair == 2) ? Wr2 : Wr3;
    __half tmp[8];
#pragma unroll
    for (int j = 0; j < 8; j++) {
        int k = kc + j;
        float v = (k < 128) ? Wl[(size_t)k * 128 + n] : Wr[(size_t)(k - 128) * 128 + n];
        tmp[j] = __float2half_rn(v);
    }
    *(uint4*)(g_w16 + ((size_t)pair * 128 + n) * 256 + kc) = *(uint4*)tmp;
}

// ---------------- CSR build ----------------
__global__ void zero_deg_kernel() {
    int i = blockIdx.x * blockDim.x + threadIdx.x;
    int stride = gridDim.x * blockDim.x;
    for (int j = i; j < NUSER; j += stride) g_deg_u[j] = 0;
    for (int j = i; j < NREPO; j += stride) g_deg_r[j] = 0;
}

__global__ void degree_kernel(const void* __restrict__ edges) {
    int is64 = g_is64;
    int stride = gridDim.x * blockDim.x;
    for (int i = blockIdx.x * blockDim.x + threadIdx.x; i < NEDGE; i += stride) {
        int u = clampi(edge_at(edges, 0, i, is64), NUSER);
        int r = clampi(edge_at(edges, 1, i, is64), NREPO);
        atomicAdd(&g_deg_u[u], 1);
        atomicAdd(&g_deg_r[r], 1);
    }
}

__global__ void scan1_kernel() {
    int side = blockIdx.y;
    int nb = side ? NB_R : NB_U;
    int b = blockIdx.x;
    if (b >= nb) return;
    int n = side ? NREPO : NUSER;
    const int* deg = side ? g_deg_r : g_deg_u;
    int* rp = side ? g_rp_r : g_rp_u;

    int tid = threadIdx.x;
    int lane = tid & 31, w = tid >> 5;
    int base = b * SCHUNK + tid * 4;

    int v[4];
    int t = 0;
#pragma unroll
    for (int j = 0; j < 4; j++) {
        int i = base + j;
        v[j] = (i < n) ? deg[i] : 0;
        t += v[j];
    }
    __shared__ int wsum[32];
    int inc = t;
#pragma unroll
    for (int o = 1; o < 32; o <<= 1) {
        int x = __shfl_up_sync(~0u, inc, o);
        if (lane >= o) inc += x;
    }
    if (lane == 31) wsum[w] = inc;
    __syncthreads();
    if (w == 0) {
        int s = wsum[lane];
#pragma unroll
        for (int o = 1; o < 32; o <<= 1) {
            int x = __shfl_up_sync(~0u, s, o);
            if (lane >= o) s += x;
        }
        wsum[lane] = s;
    }
    __syncthreads();
    int ex = inc - t + (w > 0 ? wsum[w - 1] : 0);
    int run = ex;
#pragma unroll
    for (int j = 0; j < 4; j++) {
        int i = base + j;
        if (i < n) rp[i] = run;
        run += v[j];
    }
    if (tid == 1023) g_bsum[side * 64 + b] = run;
}

__global__ void scan2_kernel() {
    int tid = threadIdx.x;
    if (tid < 2) {
        int nb = tid ? NB_R : NB_U;
        int* bs = g_bsum + tid * 64;
        int s = 0;
        for (int i = 0; i < nb; i++) { int x = bs[i]; bs[i] = s; s += x; }
    }
}

__global__ void scan3_kernel() {
    int side = blockIdx.y;
    int nb = side ? NB_R : NB_U;
    int b = blockIdx.x;
    if (b >= nb) return;
    int n = side ? NREPO : NUSER;
    int* rp = side ? g_rp_r : g_rp_u;
    int* fill = side ? g_fill_r : g_fill_u;
    int off = g_bsum[side * 64 + b];
    int base = b * SCHUNK + threadIdx.x * 4;
#pragma unroll
    for (int j = 0; j < 4; j++) {
        int i = base + j;
        if (i < n) {
            int x = rp[i] + off;
            rp[i] = x;
            fill[i] = x;
        }
    }
    if (b == 0 && threadIdx.x == 0) rp[n] = NEDGE;
}

__global__ void place_kernel(const void* __restrict__ edges) {
    int is64 = g_is64;
    int stride = gridDim.x * blockDim.x;
    for (int i = blockIdx.x * blockDim.x + threadIdx.x; i < NEDGE; i += stride) {
        int u = clampi(edge_at(edges, 0, i, is64), NUSER);
        int r = clampi(edge_at(edges, 1, i, is64), NREPO);
        g_adj_r[atomicAdd(&g_fill_r[r], 1)] = u;
        g_adj_u[atomicAdd(&g_fill_u[u], 1)] = r;
    }
}

// ---------------- dual gather-mean (fp16 src -> fp16 mean) ----------------
__global__ void gather_dual_kernel(int layer) {
    int gw = (blockIdx.x * blockDim.x + threadIdx.x) >> 5;
    int lane = threadIdx.x & 31;

    const __half* src;
    __half* dst;
    const int* rp;
    const int* adj;
    int row;
    if (gw < NREPO) {
        row = gw;
        src = (layer == 1) ? g_x16_u : g_h16_u;
        dst = g_m16_r;
        rp = g_rp_r;
        adj = g_adj_r;
    } else {
        row = gw - NREPO;
        if (row >= NUSER) return;
        src = (layer == 1) ? g_x16_r : g_h16_r;
        dst = g_m16_u;
        rp = g_rp_u;
        adj = g_adj_u;
    }

    int beg = rp[row], end = rp[row + 1];
    float4 a0 = make_float4(0.f, 0.f, 0.f, 0.f);
    float4 a1 = a0, a2 = a0, a3 = a0;

    int j = beg;
    for (; j + 4 <= end; j += 4) {
        int n0 = adj[j], n1 = adj[j + 1], n2 = adj[j + 2], n3 = adj[j + 3];
        uint2 w0 = ((const uint2*)(src + (size_t)n0 * DD))[lane];
        uint2 w1 = ((const uint2*)(src + (size_t)n1 * DD))[lane];
        uint2 w2 = ((const uint2*)(src + (size_t)n2 * DD))[lane];
        uint2 w3 = ((const uint2*)(src + (size_t)n3 * DD))[lane];
        float2 f;
        f = __half22float2(*(__half2*)&w0.x); a0.x += f.x; a0.y += f.y;
        f = __half22float2(*(__half2*)&w0.y); a0.z += f.x; a0.w += f.y;
        f = __half22float2(*(__half2*)&w1.x); a1.x += f.x; a1.y += f.y;
        f = __half22float2(*(__half2*)&w1.y); a1.z += f.x; a1.w += f.y;
        f = __half22float2(*(__half2*)&w2.x); a2.x += f.x; a2.y += f.y;
        f = __half22float2(*(__half2*)&w2.y); a2.z += f.x; a2.w += f.y;
        f = __half22float2(*(__half2*)&w3.x); a3.x += f.x; a3.y += f.y;
        f = __half22float2(*(__half2*)&w3.y); a3.z += f.x; a3.w += f.y;
    }
    for (; j < end; j++) {
        uint2 w = ((const uint2*)(src + (size_t)adj[j] * DD))[lane];
        float2 f;
        f = __half22float2(*(__half2*)&w.x); a0.x += f.x; a0.y += f.y;
        f = __half22float2(*(__half2*)&w.y); a0.z += f.x; a0.w += f.y;
    }
    float4 s;
    s.x = (a0.x + a1.x) + (a2.x + a3.x);
    s.y = (a0.y + a1.y) + (a2.y + a3.y);
    s.z = (a0.z + a1.z) + (a2.z + a3.z);
    s.w = (a0.w + a1.w) + (a2.w + a3.w);
    float sc = 1.f / (float)max(end - beg, 1);
    __half2 h0 = __floats2half2_rn(s.x * sc, s.y * sc);
    __half2 h1 = __floats2half2_rn(s.z * sc, s.w * sc);
    uint2 o;
    o.x = *(unsigned*)&h0;
    o.y = *(unsigned*)&h1;
    ((uint2*)(dst + (size_t)row * DD))[lane] = o;
}

// ---------------- fp16 fused SAGE GEMM: m16n8k16, BM=128, K=256 -------------
__device__ __forceinline__ void mma_f16(float c[4], const unsigned a[4], const unsigned b[2]) {
    asm volatile(
        "mma.sync.aligned.m16n8k16.row.col.f32.f16.f16.f32 "
        "{%0,%1,%2,%3}, {%4,%5,%6,%7}, {%8,%9}, {%0,%1,%2,%3};"
        : "+f"(c[0]), "+f"(c[1]), "+f"(c[2]), "+f"(c[3])
        : "r"(a[0]), "r"(a[1]), "r"(a[2]), "r"(a[3]), "r"(b[0]), "r"(b[1]));
}

#define PA 72    // halves pitch for A chunk rows (BK=64 + 8 pad)
#define PW 264   // halves pitch for W rows (K=256 + 8 pad)
#define SMEM_H (128 * PW + 2 * 128 * PA)   // halves

template <bool RELU>
__global__ void __launch_bounds__(256, 1)
gemm_h(int meanRepo,            // 1 -> g_m16_r, 0 -> g_m16_u
       int xSel,                // 0 x16_u, 1 x16_r, 2 h16_u, 3 h16_r
       int pair,                // weight pair index into g_w16
       const float* __restrict__ bias,
       float* __restrict__ ext_out,   // fp32 output (outSel==0)
       int outSel,              // 0 ext fp32, 1 h16_u, 2 h16_r
       int rows) {
    extern __shared__ __half sh[];
    __half* sW = sh;                    // [128][PW]
    __half* sA = sh + 128 * PW;         // 2 x [128][PA]

    const __half* meanp = meanRepo ? g_m16_r : g_m16_u;
    const __half* xp = (xSel == 0) ? g_x16_u : (xSel == 1) ? g_x16_r
                     : (xSel == 2) ? g_h16_u : g_h16_r;
    const __half* w16 = g_w16 + (size_t)pair * 128 * 256;
    float* out = (outSel == 0) ? ext_out : nullptr;
    __half* out16 = (outSel == 1) ? g_h16_u : (outSel == 2) ? g_h16_r : nullptr;

    const int tid = threadIdx.x;
    const int lane = tid & 31;
    const int warp = tid >> 5;
    const int wm = (warp >> 2) * 64;
    const int wn = (warp & 3) * 32;
    const int blockRow = blockIdx.x * 128;

    // load W tile: 256 threads, thread t -> row t>>1, half-row (t&1)*16 uint4.
    // full row = 256 halves = 32 uint4 = 512 B.
    {
        int wrow = tid >> 1;
        int off = (tid & 1) * 16;   // in uint4 units
        const uint4* src = (const uint4*)(w16 + (size_t)wrow * 256) + off;
        uint4* dst = (uint4*)(sW + (size_t)wrow * PW) + off;
#pragma unroll
        for (int q = 0; q < 16; q++) dst[q] = src[q];
    }

    const int lr = tid >> 1;            // 0..127 (one row per 2 threads)
    const int ch32 = (tid & 1) * 32;    // half-offset within 64-half chunk
    const int crow = min(blockRow + lr, rows - 1);

    float cfr[4][4][4];
#pragma unroll
    for (int f = 0; f < 4; f++)
#pragma unroll
        for (int g = 0; g < 4; g++)
#pragma unroll
            for (int k = 0; k < 4; k++) cfr[f][g][k] = 0.f;

    auto loadch = [&](int ch, uint4 v[4]) {
        const __half* src = (ch < 2) ? meanp : xp;
        int col = (ch & 1) * 64 + ch32;
        const uint4* p = (const uint4*)(src + (size_t)crow * DD + col);
#pragma unroll
        for (int q = 0; q < 4; q++) v[q] = p[q];
    };
    auto storech = [&](int buf, uint4 v[4]) {
        uint4* base = (uint4*)(sA + (size_t)buf * (128 * PA) + (size_t)lr * PA + ch32);
#pragma unroll
        for (int q = 0; q < 4; q++) base[q] = v[q];
    };

    uint4 cur[4];
    loadch(0, cur);
    storech(0, cur);
    __syncthreads();

#pragma unroll 1
    for (int ch = 0; ch < 4; ch++) {
        uint4 nxt[4];
        if (ch < 3) loadch(ch + 1, nxt);

        const __half* Ab = sA + (ch & 1) * (128 * PA);
        const __half* Wb = sW + ch * 64;   // k-offset within W rows

#pragma unroll
        for (int s = 0; s < 4; s++) {
            const int k0 = s * 16 + (lane & 3) * 2;
            unsigned a[4][4], b[4][2];
#pragma unroll
            for (int f = 0; f < 4; f++) {
                const __half* ab = Ab + (size_t)(wm + f * 16 + (lane >> 2)) * PA + k0;
                a[f][0] = *(const unsigned*)(ab);
                a[f][1] = *(const unsigned*)(ab + 8 * PA);
                a[f][2] = *(const unsigned*)(ab + 8);
                a[f][3] = *(const unsigned*)(ab + 8 * PA + 8);
            }
#pragma unroll
            for (int g = 0; g < 4; g++) {
                const __half* bb = Wb + (size_t)(wn + g * 8 + (lane >> 2)) * PW + k0;
                b[g][0] = *(const unsigned*)(bb);
                b[g][1] = *(const unsigned*)(bb + 8);
            }
#pragma unroll
            for (int f = 0; f < 4; f++)
#pragma unroll
                for (int g = 0; g < 4; g++) mma_f16(cfr[f][g], a[f], b[g]);
        }

        if (ch < 3) storech((ch + 1) & 1, nxt);
        __syncthreads();
    }

    // epilogue: bias (+relu); fp32 final write or fp16 hidden write
#pragma unroll
    for (int f = 0; f < 4; f++) {
        int r0 = blockRow + wm + f * 16 + (lane >> 2);
#pragma unroll
        for (int g = 0; g < 4; g++) {
            int c = wn + g * 8 + (lane & 3) * 2;
            float b0 = bias[c], b1 = bias[c + 1];
            if (r0 < rows) {
                float v0 = cfr[f][g][0] + b0;
                float v1 = cfr[f][g][1] + b1;
                if (RELU) { v0 = fmaxf(v0, 0.f); v1 = fmaxf(v1, 0.f); }
                if (out) {
                    out[(size_t)r0 * DD + c] = v0;
                    out[(size_t)r0 * DD + c + 1] = v1;
                }
                if (out16)
                    *(__half2*)(out16 + (size_t)r0 * DD + c) = __floats2half2_rn(v0, v1);
            }
            if (r0 + 8 < rows) {
                float v2 = cfr[f][g][2] + b0;
                float v3 = cfr[f][g][3] + b1;
                if (RELU) { v2 = fmaxf(v2, 0.f); v3 = fmaxf(v3, 0.f); }
                if (out) {
                    out[(size_t)(r0 + 8) * DD + c] = v2;
                    out[(size_t)(r0 + 8) * DD + c + 1] = v3;
                }
                if (out16)
                    *(__half2*)(out16 + (size_t)(r0 + 8) * DD + c) = __floats2half2_rn(v2, v3);
            }
        }
    }
}

// ---------------- launch ----------------
extern "C" void kernel_launch(void* const* d_in, const int* in_sizes, int n_in,
                              void* d_out, int out_size) {
    const float* x_user = (const float*)d_in[0];
    const float* x_repo = (const float*)d_in[1];
    const void* edges = d_in[2];
    const float* Wl1s = (const float*)d_in[3];
    const float* bl1s = (const float*)d_in[4];
    const float* Wr1s = (const float*)d_in[5];
    const float* Wl1r = (const float*)d_in[6];
    const float* bl1r = (const float*)d_in[7];
    const float* Wr1r = (const float*)d_in[8];
    const float* Wl2s = (const float*)d_in[9];
    const float* bl2s = (const float*)d_in[10];
    const float* Wr2s = (const float*)d_in[11];
    const float* Wl2r = (const float*)d_in[12];
    const float* bl2r = (const float*)d_in[13];
    const float* Wr2r = (const float*)d_in[14];

    float* out_user = (float*)d_out;
    float* out_repo = out_user + (size_t)NUSER * DD;

    const int smem = SMEM_H * (int)sizeof(__half);   // 104448 B
    cudaFuncSetAttribute(gemm_h<true>, cudaFuncAttributeMaxDynamicSharedMemorySize, smem);
    cudaFuncSetAttribute(gemm_h<false>, cudaFuncAttributeMaxDynamicSharedMemorySize, smem);

    // ---- probe + fp16 copies + weight prep + CSR build ----
    probe_kernel<<<1, 256>>>((const int*)edges);
    tohalf_kernel<<<2048, 256>>>(x_user, x_repo);
    wprep_kernel<<<64, 256>>>(Wl1s, Wr1s, Wl1r, Wr1r, Wl2s, Wr2s, Wl2r, Wr2r);
    zero_deg_kernel<<<512, 512>>>();
    degree_kernel<<<2048, 256>>>(edges);
    dim3 gs(NB_U, 2);
    scan1_kernel<<<gs, 1024>>>();
    scan2_kernel<<<1, 32>>>();
    scan3_kernel<<<gs, 1024>>>();
    place_kernel<<<2048, 256>>>(edges);

    const int gwarps = NREPO + NUSER;
    const int gblocks = (gwarps * 32 + 255) / 256;

    // ---- layer 1 ----
    gather_dual_kernel<<<gblocks, 256>>>(1);
    gemm_h<true><<<(NREPO + 127) / 128, 256, smem>>>(
        1, 1, 0, bl1s, nullptr, 2, NREPO);
    gemm_h<true><<<(NUSER + 127) / 128, 256, smem>>>(
        0, 0, 1, bl1r, nullptr, 1, NUSER);

    // ---- layer 2 ----
    gather_dual_kernel<<<gblocks, 256>>>(2);
    gemm_h<false><<<(NREPO + 127) / 128, 256, smem>>>(
        1, 3, 2, bl2s, out_repo, 0, NREPO);
    gemm_h<false><<<(NUSER + 127) / 128, 256, smem>>>(
        0, 2, 3, bl2r, out_user, 0, NUSER);
}

// round 15
// speedup vs baseline: 2.1633x; 1.5225x over previous
#include <cuda_runtime.h>
#include <cuda_fp16.h>
#include <cstdint>

#define NUSER 200000
#define NREPO 100000
#define NEDGE 1500000
#define DD    128
#define SCHUNK 4096
#define NB_U ((NUSER + SCHUNK - 1) / SCHUNK)   // 49
#define NB_R ((NREPO + SCHUNK - 1) / SCHUNK)   // 25
#define RHALF ((NREPO + 1) / 2)
#define UHALF ((NUSER + 1) / 2)
#define RBLK ((NREPO + 127) / 128)
#define UBLK ((NUSER + 127) / 128)

// ---------------- scratch (__device__ globals; no allocations) ----------------
__device__ int g_is64;
__device__ int g_deg_u[NUSER];
__device__ int g_deg_r[NREPO];
__device__ int g_rp_u[NUSER + 1];
__device__ int g_rp_r[NREPO + 1];
__device__ int g_fill_u[NUSER];
__device__ int g_fill_r[NREPO];
__device__ int g_adj_u[NEDGE];
__device__ int g_adj_r[NEDGE];
__device__ int g_bsum[2 * 64];
// fp16 node features / hidden / means
__device__ __align__(128) __half g_x16_u[(size_t)NUSER * DD];
__device__ __align__(128) __half g_x16_r[(size_t)NREPO * DD];
__device__ __align__(128) __half g_h16_u[(size_t)NUSER * DD];
__device__ __align__(128) __half g_h16_r[(size_t)NREPO * DD];
__device__ __align__(128) __half g_m16_u[(size_t)NUSER * DD];
__device__ __align__(128) __half g_m16_r[(size_t)NREPO * DD];
// fp16 weights, transposed: [pair][n=128][k=256], k = [Wl rows | Wr rows]
__device__ __align__(128) __half g_w16[4 * 128 * 256];

// ---------------- edge dtype probe + accessors ----------------
__global__ void probe_kernel(const int* __restrict__ e32) {
    __shared__ int nonzero;
    if (threadIdx.x == 0) nonzero = 0;
    __syncthreads();
    if (e32[threadIdx.x * 2 + 1] != 0) atomicOr(&nonzero, 1);
    __syncthreads();
    if (threadIdx.x == 0) g_is64 = (nonzero ? 0 : 1);
}

__device__ __forceinline__ int edge_at(const void* edges, int row, int i, int is64) {
    if (is64) {
        long long v = ((const long long*)edges)[(size_t)row * NEDGE + i];
        return (int)v;
    }
    return ((const int*)edges)[(size_t)row * NEDGE + i];
}

__device__ __forceinline__ int clampi(int v, int hi) {
    return v < 0 ? 0 : (v >= hi ? hi - 1 : v);
}

// ---------------- fp32 -> fp16 conversion of inputs ----------------
__global__ void tohalf_kernel(const float* __restrict__ xu,
                              const float* __restrict__ xr) {
    const size_t nu4 = (size_t)NUSER * DD / 4;
    const size_t nr4 = (size_t)NREPO * DD / 4;
    size_t stride = (size_t)gridDim.x * blockDim.x;
    for (size_t i = (size_t)blockIdx.x * blockDim.x + threadIdx.x;
         i < nu4 + nr4; i += stride) {
        const float4* src;
        uint2* dst;
        size_t j;
        if (i < nu4) { src = (const float4*)xu; dst = (uint2*)g_x16_u; j = i; }
        else         { src = (const float4*)xr; dst = (uint2*)g_x16_r; j = i - nu4; }
        float4 v = src[j];
        __half2 h0 = __floats2half2_rn(v.x, v.y);
        __half2 h1 = __floats2half2_rn(v.z, v.w);
        uint2 o;
        o.x = *(unsigned*)&h0;
        o.y = *(unsigned*)&h1;
        dst[j] = o;
    }
}

// ---------------- weight prep: fp32 [k][n] pairs -> fp16 [n][k] ----------------
__global__ void wprep_kernel(const float* __restrict__ Wl0, const float* __restrict__ Wr0,
                             const float* __restrict__ Wl1, const float* __restrict__ Wr1,
                             const float* __restrict__ Wl2, const float* __restrict__ Wr2,
                             const float* __restrict__ Wl3, const float* __restrict__ Wr3) {
    int idx = blockIdx.x * blockDim.x + threadIdx.x;  // 16384 threads
    if (idx >= 4 * 32 * 128) return;
    int n = idx & 127;
    int kc = ((idx >> 7) & 31) * 8;
    int pair = idx >> 12;
    const float* Wl = (pair == 0) ? Wl0 : (pair == 1) ? Wl1 : (pair == 2) ? Wl2 : Wl3;
    const float* Wr = (pair == 0) ? Wr0 : (pair == 1) ? Wr1 : (pair == 2) ? Wr2 : Wr3;
    __half tmp[8];
#pragma unroll
    for (int j = 0; j < 8; j++) {
        int k = kc + j;
        float v = (k < 128) ? Wl[(size_t)k * 128 + n] : Wr[(size_t)(k - 128) * 128 + n];
        tmp[j] = __float2half_rn(v);
    }
    *(uint4*)(g_w16 + ((size_t)pair * 128 + n) * 256 + kc) = *(uint4*)tmp;
}

// ---------------- CSR build ----------------
__global__ void zero_deg_kernel() {
    int i = blockIdx.x * blockDim.x + threadIdx.x;
    int stride = gridDim.x * blockDim.x;
    for (int j = i; j < NUSER; j += stride) g_deg_u[j] = 0;
    for (int j = i; j < NREPO; j += stride) g_deg_r[j] = 0;
}

__global__ void degree_kernel(const void* __restrict__ edges) {
    int is64 = g_is64;
    int stride = gridDim.x * blockDim.x;
    for (int i = blockIdx.x * blockDim.x + threadIdx.x; i < NEDGE; i += stride) {
        int u = clampi(edge_at(edges, 0, i, is64), NUSER);
        int r = clampi(edge_at(edges, 1, i, is64), NREPO);
        atomicAdd(&g_deg_u[u], 1);
        atomicAdd(&g_deg_r[r], 1);
    }
}

__global__ void scan1_kernel() {
    int side = blockIdx.y;
    int nb = side ? NB_R : NB_U;
    int b = blockIdx.x;
    if (b >= nb) return;
    int n = side ? NREPO : NUSER;
    const int* deg = side ? g_deg_r : g_deg_u;
    int* rp = side ? g_rp_r : g_rp_u;

    int tid = threadIdx.x;
    int lane = tid & 31, w = tid >> 5;
    int base = b * SCHUNK + tid * 4;

    int v[4];
    int t = 0;
#pragma unroll
    for (int j = 0; j < 4; j++) {
        int i = base + j;
        v[j] = (i < n) ? deg[i] : 0;
        t += v[j];
    }
    __shared__ int wsum[32];
    int inc = t;
#pragma unroll
    for (int o = 1; o < 32; o <<= 1) {
        int x = __shfl_up_sync(~0u, inc, o);
        if (lane >= o) inc += x;
    }
    if (lane == 31) wsum[w] = inc;
    __syncthreads();
    if (w == 0) {
        int s = wsum[lane];
#pragma unroll
        for (int o = 1; o < 32; o <<= 1) {
            int x = __shfl_up_sync(~0u, s, o);
            if (lane >= o) s += x;
        }
        wsum[lane] = s;
    }
    __syncthreads();
    int ex = inc - t + (w > 0 ? wsum[w - 1] : 0);
    int run = ex;
#pragma unroll
    for (int j = 0; j < 4; j++) {
        int i = base + j;
        if (i < n) rp[i] = run;
        run += v[j];
    }
    if (tid == 1023) g_bsum[side * 64 + b] = run;
}

__global__ void scan2_kernel() {
    int tid = threadIdx.x;
    if (tid < 2) {
        int nb = tid ? NB_R : NB_U;
        int* bs = g_bsum + tid * 64;
        int s = 0;
        for (int i = 0; i < nb; i++) { int x = bs[i]; bs[i] = s; s += x; }
    }
}

__global__ void scan3_kernel() {
    int side = blockIdx.y;
    int nb = side ? NB_R : NB_U;
    int b = blockIdx.x;
    if (b >= nb) return;
    int n = side ? NREPO : NUSER;
    int* rp = side ? g_rp_r : g_rp_u;
    int* fill = side ? g_fill_r : g_fill_u;
    int off = g_bsum[side * 64 + b];
    int base = b * SCHUNK + threadIdx.x * 4;
#pragma unroll
    for (int j = 0; j < 4; j++) {
        int i = base + j;
        if (i < n) {
            int x = rp[i] + off;
            rp[i] = x;
            fill[i] = x;
        }
    }
    if (b == 0 && threadIdx.x == 0) rp[n] = NEDGE;
}

__global__ void place_kernel(const void* __restrict__ edges) {
    int is64 = g_is64;
    int stride = gridDim.x * blockDim.x;
    for (int i = blockIdx.x * blockDim.x + threadIdx.x; i < NEDGE; i += stride) {
        int u = clampi(edge_at(edges, 0, i, is64), NUSER);
        int r = clampi(edge_at(edges, 1, i, is64), NREPO);
        g_adj_r[atomicAdd(&g_fill_r[r], 1)] = u;
        g_adj_u[atomicAdd(&g_fill_u[u], 1)] = r;
    }
}

// ---------------- dual-row gather-mean: one warp per TWO dst rows -----------
// Doubles memory-level parallelism for short rows: joint loop keeps 4 row
// loads in flight (2 per row), remainder loops use 4-way per row.
__device__ __forceinline__ void acc_row(float4& A, uint2 w) {
    float2 f = __half22float2(*(__half2*)&w.x);
    A.x += f.x; A.y += f.y;
    f = __half22float2(*(__half2*)&w.y);
    A.z += f.x; A.w += f.y;
}

template <int LAYER>
__global__ void gather_dual2_kernel() {
    int gw = (blockIdx.x * blockDim.x + threadIdx.x) >> 5;
    int lane = threadIdx.x & 31;

    const __half* src;
    __half* dst;
    const int* rp;
    const int* adj;
    int rA, rB, nrows;
    if (gw < RHALF) {
        rA = gw; rB = gw + RHALF; nrows = NREPO;
        src = (LAYER == 1) ? g_x16_u : g_h16_u;
        dst = g_m16_r; rp = g_rp_r; adj = g_adj_r;
    } else {
        gw -= RHALF;
        if (gw >= UHALF) return;
        rA = gw; rB = gw + UHALF; nrows = NUSER;
        src = (LAYER == 1) ? g_x16_r : g_h16_r;
        dst = g_m16_u; rp = g_rp_u; adj = g_adj_u;
    }
    const bool hasB = rB < nrows;

    int begA = rp[rA], endA = rp[rA + 1];
    int begB = 0, endB = 0;
    if (hasB) { begB = rp[rB], endB = rp[rB + 1]; }

    float4 xA0 = make_float4(0.f, 0.f, 0.f, 0.f), xA1 = xA0;
    float4 xB0 = xA0, xB1 = xA0;
    int jA = begA, jB = begB;

    // joint loop: 2 neighbors of A + 2 of B in flight together
    while (jA + 2 <= endA && jB + 2 <= endB) {
        int a0 = adj[jA], a1 = adj[jA + 1];
        int b0 = adj[jB], b1 = adj[jB + 1];
        uint2 wa0 = ((const uint2*)(src + (size_t)a0 * DD))[lane];
        uint2 wa1 = ((const uint2*)(src + (size_t)a1 * DD))[lane];
        uint2 wb0 = ((const uint2*)(src + (size_t)b0 * DD))[lane];
        uint2 wb1 = ((const uint2*)(src + (size_t)b1 * DD))[lane];
        acc_row(xA0, wa0); acc_row(xA1, wa1);
        acc_row(xB0, wb0); acc_row(xB1, wb1);
        jA += 2; jB += 2;
    }
    // finish A
    for (; jA + 4 <= endA; jA += 4) {
        int n0 = adj[jA], n1 = adj[jA + 1], n2 = adj[jA + 2], n3 = adj[jA + 3];
        uint2 w0 = ((const uint2*)(src + (size_t)n0 * DD))[lane];
        uint2 w1 = ((const uint2*)(src + (size_t)n1 * DD))[lane];
        uint2 w2 = ((const uint2*)(src + (size_t)n2 * DD))[lane];
        uint2 w3 = ((const uint2*)(src + (size_t)n3 * DD))[lane];
        acc_row(xA0, w0); acc_row(xA1, w1);
        acc_row(xA0, w2); acc_row(xA1, w3);
    }
    for (; jA < endA; jA++) {
        uint2 w = ((const uint2*)(src + (size_t)adj[jA] * DD))[lane];
        acc_row(xA0, w);
    }
    // finish B
    if (hasB) {
        for (; jB + 4 <= endB; jB += 4) {
            int n0 = adj[jB], n1 = adj[jB + 1], n2 = adj[jB + 2], n3 = adj[jB + 3];
            uint2 w0 = ((const uint2*)(src + (size_t)n0 * DD))[lane];
            uint2 w1 = ((const uint2*)(src + (size_t)n1 * DD))[lane];
            uint2 w2 = ((const uint2*)(src + (size_t)n2 * DD))[lane];
            uint2 w3 = ((const uint2*)(src + (size_t)n3 * DD))[lane];
            acc_row(xB0, w0); acc_row(xB1, w1);
            acc_row(xB0, w2); acc_row(xB1, w3);
        }
        for (; jB < endB; jB++) {
            uint2 w = ((const uint2*)(src + (size_t)adj[jB] * DD))[lane];
            acc_row(xB0, w);
        }
    }

    {
        float scA = 1.f / (float)max(endA - begA, 1);
        float sx = (xA0.x + xA1.x) * scA, sy = (xA0.y + xA1.y) * scA;
        float sz = (xA0.z + xA1.z) * scA, sw = (xA0.w + xA1.w) * scA;
        __half2 h0 = __floats2half2_rn(sx, sy);
        __half2 h1 = __floats2half2_rn(sz, sw);
        uint2 o; o.x = *(unsigned*)&h0; o.y = *(unsigned*)&h1;
        ((uint2*)(dst + (size_t)rA * DD))[lane] = o;
    }
    if (hasB) {
        float scB = 1.f / (float)max(endB - begB, 1);
        float sx = (xB0.x + xB1.x) * scB, sy = (xB0.y + xB1.y) * scB;
        float sz = (xB0.z + xB1.z) * scB, sw = (xB0.w + xB1.w) * scB;
        __half2 h0 = __floats2half2_rn(sx, sy);
        __half2 h1 = __floats2half2_rn(sz, sw);
        uint2 o; o.x = *(unsigned*)&h0; o.y = *(unsigned*)&h1;
        ((uint2*)(dst + (size_t)rB * DD))[lane] = o;
    }
}

// ---------------- fp16 fused SAGE GEMM: m16n8k16, BM=128, K=256 -------------
// One launch covers BOTH node types: blocks [0, RBLK) -> repo, rest -> user.
__device__ __forceinline__ void mma_f16(float c[4], const unsigned a[4], const unsigned b[2]) {
    asm volatile(
        "mma.sync.aligned.m16n8k16.row.col.f32.f16.f16.f32 "
        "{%0,%1,%2,%3}, {%4,%5,%6,%7}, {%8,%9}, {%0,%1,%2,%3};"
        : "+f"(c[0]), "+f"(c[1]), "+f"(c[2]), "+f"(c[3])
        : "r"(a[0]), "r"(a[1]), "r"(a[2]), "r"(a[3]), "r"(b[0]), "r"(b[1]));
}

#define PA 72    // halves pitch for A chunk rows (BK=64 + 8 pad)
#define PW 264   // halves pitch for W rows (K=256 + 8 pad)
#define SMEM_H (128 * PW + 2 * 128 * PA)   // halves

template <int LAYER>
__global__ void __launch_bounds__(256, 1)
gemm_dual(const float* __restrict__ biasR,
          const float* __restrict__ biasU,
          float* __restrict__ outR32,
          float* __restrict__ outU32) {
    extern __shared__ __half sh[];
    __half* sW = sh;                    // [128][PW]
    __half* sA = sh + 128 * PW;         // 2 x [128][PA]

    const bool isRepo = blockIdx.x < RBLK;
    const int blockRow = (isRepo ? blockIdx.x : blockIdx.x - RBLK) * 128;
    const int rows = isRepo ? NREPO : NUSER;
    const __half* meanp = isRepo ? g_m16_r : g_m16_u;
    const __half* xp = (LAYER == 1) ? (isRepo ? g_x16_r : g_x16_u)
                                    : (isRepo ? g_h16_r : g_h16_u);
    const int pair = (LAYER == 1) ? (isRepo ? 0 : 1) : (isRepo ? 2 : 3);
    const __half* w16 = g_w16 + (size_t)pair * 128 * 256;
    const float* bias = isRepo ? biasR : biasU;
    float* out = (LAYER == 2) ? (isRepo ? outR32 : outU32) : nullptr;
    __half* out16 = (LAYER == 1) ? (isRepo ? g_h16_r : g_h16_u) : nullptr;

    const int tid = threadIdx.x;
    const int lane = tid & 31;
    const int warp = tid >> 5;
    const int wm = (warp >> 2) * 64;
    const int wn = (warp & 3) * 32;

    // load W tile: 256 threads, thread t -> row t>>1, half-row (t&1)*16 uint4
    {
        int wrow = tid >> 1;
        int off = (tid & 1) * 16;
        const uint4* src = (const uint4*)(w16 + (size_t)wrow * 256) + off;
        uint4* dstp = (uint4*)(sW + (size_t)wrow * PW) + off;
#pragma unroll
        for (int q = 0; q < 16; q++) dstp[q] = src[q];
    }

    const int lr = tid >> 1;
    const int ch32 = (tid & 1) * 32;
    const int crow = min(blockRow + lr, rows - 1);

    float cfr[4][4][4];
#pragma unroll
    for (int f = 0; f < 4; f++)
#pragma unroll
        for (int g = 0; g < 4; g++)
#pragma unroll
            for (int k = 0; k < 4; k++) cfr[f][g][k] = 0.f;

    auto loadch = [&](int ch, uint4 v[4]) {
        const __half* src = (ch < 2) ? meanp : xp;
        int col = (ch & 1) * 64 + ch32;
        const uint4* p = (const uint4*)(src + (size_t)crow * DD + col);
#pragma unroll
        for (int q = 0; q < 4; q++) v[q] = p[q];
    };
    auto storech = [&](int buf, uint4 v[4]) {
        uint4* base = (uint4*)(sA + (size_t)buf * (128 * PA) + (size_t)lr * PA + ch32);
#pragma unroll
        for (int q = 0; q < 4; q++) base[q] = v[q];
    };

    uint4 cur[4];
    loadch(0, cur);
    storech(0, cur);
    __syncthreads();

#pragma unroll 1
    for (int ch = 0; ch < 4; ch++) {
        uint4 nxt[4];
        if (ch < 3) loadch(ch + 1, nxt);

        const __half* Ab = sA + (ch & 1) * (128 * PA);
        const __half* Wb = sW + ch * 64;

#pragma unroll
        for (int s = 0; s < 4; s++) {
            const int k0 = s * 16 + (lane & 3) * 2;
            unsigned a[4][4], b[4][2];
#pragma unroll
            for (int f = 0; f < 4; f++) {
                const __half* ab = Ab + (size_t)(wm + f * 16 + (lane >> 2)) * PA + k0;
                a[f][0] = *(const unsigned*)(ab);
                a[f][1] = *(const unsigned*)(ab + 8 * PA);
                a[f][2] = *(const unsigned*)(ab + 8);
                a[f][3] = *(const unsigned*)(ab + 8 * PA + 8);
            }
#pragma unroll
            for (int g = 0; g < 4; g++) {
                const __half* bb = Wb + (size_t)(wn + g * 8 + (lane >> 2)) * PW + k0;
                b[g][0] = *(const unsigned*)(bb);
                b[g][1] = *(const unsigned*)(bb + 8);
            }
#pragma unroll
            for (int f = 0; f < 4; f++)
#pragma unroll
                for (int g = 0; g < 4; g++) mma_f16(cfr[f][g], a[f], b[g]);
        }

        if (ch < 3) storech((ch + 1) & 1, nxt);
        __syncthreads();
    }

    // epilogue: bias (+relu on layer 1); fp32 final or fp16 hidden write
#pragma unroll
    for (int f = 0; f < 4; f++) {
        int r0 = blockRow + wm + f * 16 + (lane >> 2);
#pragma unroll
        for (int g = 0; g < 4; g++) {
            int c = wn + g * 8 + (lane & 3) * 2;
            float b0 = bias[c], b1 = bias[c + 1];
            if (r0 < rows) {
                float v0 = cfr[f][g][0] + b0;
                float v1 = cfr[f][g][1] + b1;
                if (LAYER == 1) { v0 = fmaxf(v0, 0.f); v1 = fmaxf(v1, 0.f); }
                if (LAYER == 2) {
                    out[(size_t)r0 * DD + c] = v0;
                    out[(size_t)r0 * DD + c + 1] = v1;
                } else {
                    *(__half2*)(out16 + (size_t)r0 * DD + c) = __floats2half2_rn(v0, v1);
                }
            }
            if (r0 + 8 < rows) {
                float v2 = cfr[f][g][2] + b0;
                float v3 = cfr[f][g][3] + b1;
                if (LAYER == 1) { v2 = fmaxf(v2, 0.f); v3 = fmaxf(v3, 0.f); }
                if (LAYER == 2) {
                    out[(size_t)(r0 + 8) * DD + c] = v2;
                    out[(size_t)(r0 + 8) * DD + c + 1] = v3;
                } else {
                    *(__half2*)(out16 + (size_t)(r0 + 8) * DD + c) = __floats2half2_rn(v2, v3);
                }
            }
        }
    }
}

// ---------------- launch ----------------
extern "C" void kernel_launch(void* const* d_in, const int* in_sizes, int n_in,
                              void* d_out, int out_size) {
    const float* x_user = (const float*)d_in[0];
    const float* x_repo = (const float*)d_in[1];
    const void* edges = d_in[2];
    const float* bl1s = (const float*)d_in[4];
    const float* bl1r = (const float*)d_in[7];
    const float* bl2s = (const float*)d_in[10];
    const float* bl2r = (const float*)d_in[13];

    float* out_user = (float*)d_out;
    float* out_repo = out_user + (size_t)NUSER * DD;

    const int smem = SMEM_H * (int)sizeof(__half);   // 104448 B
    cudaFuncSetAttribute(gemm_dual<1>, cudaFuncAttributeMaxDynamicSharedMemorySize, smem);
    cudaFuncSetAttribute(gemm_dual<2>, cudaFuncAttributeMaxDynamicSharedMemorySize, smem);

    // ---- probe + fp16 copies + weight prep + CSR build ----
    probe_kernel<<<1, 256>>>((const int*)edges);
    tohalf_kernel<<<2048, 256>>>(x_user, x_repo);
    wprep_kernel<<<64, 256>>>((const float*)d_in[3], (const float*)d_in[5],
                              (const float*)d_in[6], (const float*)d_in[8],
                              (const float*)d_in[9], (const float*)d_in[11],
                              (const float*)d_in[12], (const float*)d_in[14]);
    zero_deg_kernel<<<512, 512>>>();
    degree_kernel<<<2048, 256>>>(edges);
    dim3 gs(NB_U, 2);
    scan1_kernel<<<gs, 1024>>>();
    scan2_kernel<<<1, 32>>>();
    scan3_kernel<<<gs, 1024>>>();
    place_kernel<<<2048, 256>>>(edges);

    const int gwarps = RHALF + UHALF;
    const int gblocks = (gwarps * 32 + 255) / 256;

    // ---- layer 1 ----
    gather_dual2_kernel<1><<<gblocks, 256>>>();
    gemm_dual<1><<<RBLK + UBLK, 256, smem>>>(bl1s, bl1r, nullptr, nullptr);

    // ---- layer 2 ----
    gather_dual2_kernel<2><<<gblocks, 256>>>();
    gemm_dual<2><<<RBLK + UBLK, 256, smem>>>(bl2s, bl2r, out_repo, out_user);
}